// round 11
// baseline (speedup 1.0000x reference)
#include <cuda_runtime.h>
#include <cuda_fp16.h>
#include <cuda_bf16.h>
#include <cstdint>

#define NN 10000
#define BB 4
#define EE 160000
#define DD 128
#define HH 4
#define OO 64
#define HO 256            // H*O
#define MM (BB*NN)        // 40000 rows
#define CSRB 625          // csr_kernel grid size (625*256 == EE)

// ---------------- scratch (device globals; no allocation allowed) ----------
__device__ __half g_hh[(size_t)MM * HO];   // projected features, fp16 [b*N+n][h*64+o]
__device__ float g_asrc[MM * HH];          // [b*N+n][h]
__device__ float g_adst[MM * HH];
__device__ float4 g_cedge;                 // c[h] = sum_o W_edge[h,o]*att_edge[h,o]
__device__ int   g_cnt[NN];
__device__ int   g_off[NN + 1];
__device__ int   g_cur[NN];
__device__ int2  g_cs[EE];                 // packed (src, __float_as_int(ea)) per CSR slot
__device__ unsigned g_bar;                 // monotonic grid-barrier ticket counter

// ---------------- grid barrier (monotonic; safe across graph replays) -------
__device__ __forceinline__ void gridbar() {
    __syncthreads();
    if (threadIdx.x == 0) {
        __threadfence();
        unsigned ticket = atomicAdd(&g_bar, 1u);
        unsigned target = (ticket / CSRB + 1u) * CSRB;
        while (*(volatile unsigned*)&g_bar < target) __nanosleep(32);
    }
    __syncthreads();
}

// ---------------- fused CSR build: zero+detect -> hist -> scan -> scatter ----
__global__ __launch_bounds__(256) void csr_kernel(
    const int* __restrict__ ei, const float* __restrict__ ea,
    const float* __restrict__ W_edge, const float* __restrict__ att_edge) {
    __shared__ int sIs64;
    __shared__ int wsum[8];

    int tid = threadIdx.x;
    int e = blockIdx.x * 256 + tid;          // 0..EE-1 exactly

    // phase 0: per-block dtype detect + zero counters + edge loads to regs
    if (tid == 0) {
        int z = 1;
        for (int i = 1; i < 64; i += 2)
            if (ei[i] != 0) z = 0;
        sIs64 = z;
    }
    if (e < NN) g_cnt[e] = 0;                // blocks 0..39 cover all counters
    __syncthreads();
    int is64 = sIs64;

    int s, d;
    if (is64) {
        s = (int)((const long long*)ei)[e];
        d = (int)((const long long*)ei)[(size_t)EE + e];
    } else {
        s = ei[e];
        d = ei[EE + e];
    }
    s = min(max(s, 0), NN - 1);
    d = min(max(d, 0), NN - 1);
    float w = ea[e];

    gridbar();                               // counters zeroed everywhere

    // phase 1: histogram (+ cedge in block 1, independent)
    atomicAdd(&g_cnt[d], 1);
    if (blockIdx.x == 1 && tid < 128) {
        int head = tid >> 5, lane = tid & 31;
        float cs = W_edge[head * OO + lane] * att_edge[head * OO + lane]
                 + W_edge[head * OO + lane + 32] * att_edge[head * OO + lane + 32];
#pragma unroll
        for (int dd = 16; dd; dd >>= 1) cs += __shfl_xor_sync(0xffffffffu, cs, dd);
        if (lane == 0) ((float*)&g_cedge)[head] = cs;
    }

    gridbar();                               // counts complete

    // phase 2: block 0 scans the 10000 counters (40 per thread, 2 passes)
    if (blockIdx.x == 0) {
        int base = tid * 40;
        int run = 0;
        for (int i = 0; i < 40; i++) {
            int idx = base + i;
            if (idx < NN) run += g_cnt[idx];
        }
        int lane = tid & 31, wid = tid >> 5;
        int inc = run;
#pragma unroll
        for (int dd = 1; dd < 32; dd <<= 1) {
            int u = __shfl_up_sync(0xffffffffu, inc, dd);
            if (lane >= dd) inc += u;
        }
        if (lane == 31) wsum[wid] = inc;
        __syncthreads();
        if (wid == 0 && lane < 8) {
            int wv = wsum[lane];
#pragma unroll
            for (int dd = 1; dd < 8; dd <<= 1) {
                int u = __shfl_up_sync(0x000000ffu, wv, dd);
                if (lane >= dd) wv += u;
            }
            wsum[lane] = wv;
        }
        __syncthreads();
        int running = inc - run + (wid ? wsum[wid - 1] : 0);
        for (int i = 0; i < 40; i++) {
            int idx = base + i;
            if (idx < NN) {
                g_off[idx] = running;
                g_cur[idx] = running;
                running += g_cnt[idx];
            }
        }
        if (tid == 0) g_off[NN] = EE;
    }

    gridbar();                               // offsets ready

    // phase 3: scatter from registers
    int pos = atomicAdd(&g_cur[d], 1);
    g_cs[pos] = make_int2(s, __float_as_int(w));
}

// ---------------- bf16-split tensor-core GEMM + fused att epilogue ----------
// h = x @ W  (M=40000, K=128, N=256). Block tile 64x64; blockIdx.y == head.
__device__ __forceinline__ float bhi(float x) {          // bf16-truncated value
    return __uint_as_float(__float_as_uint(x) & 0xffff0000u);
}
__device__ __forceinline__ uint32_t packhi(float a, float b) {   // {a.hi16, b.hi16<<16}
    return __byte_perm(__float_as_uint(a), __float_as_uint(b), 0x7632);
}
__device__ __forceinline__ uint32_t packlo(float a, float b) {   // rn residuals
    uint32_t r;
    asm("cvt.rn.bf16x2.f32 %0, %1, %2;" : "=r"(r)
        : "f"(b - bhi(b)), "f"(a - bhi(a)));             // first src -> high half
    return r;
}

__global__ __launch_bounds__(256) void gemm_kernel(
    const float* __restrict__ A, const float* __restrict__ W,
    const float* __restrict__ att_src, const float* __restrict__ att_dst) {
    __shared__ float4 Bs[2][64][5];      // [buf][col][tig] = (bh0,bh1,bl0,bl1), pad 5
    __shared__ float red[8][8][4];

    int t = threadIdx.x;
    int w = t >> 5, lane = t & 31, gid = lane >> 2, tig = lane & 3;
    int rowBase = blockIdx.x * 64, colBase = blockIdx.y * 64;
    int warpRow = (w & 3) * 16, warpCol = (w >> 2) * 32;

    float acc[4][4];
#pragma unroll
    for (int i = 0; i < 4; i++)
#pragma unroll
        for (int j = 0; j < 4; j++) acc[i][j] = 0.f;

    int row0 = rowBase + warpRow + gid;
    int row1 = row0 + 8;
    const float* Ap0 = A + (size_t)row0 * DD + 2 * tig;
    const float* Ap1 = A + (size_t)row1 * DD + 2 * tig;

    int scol = t & 63, skk = t >> 6;                 // B stage: col, tig-slot
    const float* Wp = W + colBase + scol + (size_t)(2 * skk) * HO;

    float2 c0 = *(const float2*)(Ap0);
    float2 c1 = *(const float2*)(Ap0 + 8);
    float2 c2 = *(const float2*)(Ap1);
    float2 c3 = *(const float2*)(Ap1 + 8);
    {
        float w0 = Wp[0], w1 = Wp[HO], w2 = Wp[8 * HO], w3 = Wp[9 * HO];
        Bs[0][scol][skk] = make_float4(__uint_as_float(packhi(w0, w1)),
                                       __uint_as_float(packhi(w2, w3)),
                                       __uint_as_float(packlo(w0, w1)),
                                       __uint_as_float(packlo(w2, w3)));
    }
    __syncthreads();

#pragma unroll
    for (int kc = 0; kc < 8; kc++) {
        int buf = kc & 1;
        float2 n0, n1, n2, n3;
        float w0, w1, w2, w3;
        if (kc < 7) {                                // prefetch next A + W
            int base = (kc + 1) * 16;
            n0 = *(const float2*)(Ap0 + base);
            n1 = *(const float2*)(Ap0 + base + 8);
            n2 = *(const float2*)(Ap1 + base);
            n3 = *(const float2*)(Ap1 + base + 8);
            const float* wp = Wp + (size_t)base * HO;
            w0 = wp[0]; w1 = wp[HO]; w2 = wp[8 * HO]; w3 = wp[9 * HO];
        }

        uint32_t ah0 = packhi(c0.x, c0.y), al0 = packlo(c0.x, c0.y);
        uint32_t ah1 = packhi(c2.x, c2.y), al1 = packlo(c2.x, c2.y);
        uint32_t ah2 = packhi(c1.x, c1.y), al2 = packlo(c1.x, c1.y);
        uint32_t ah3 = packhi(c3.x, c3.y), al3 = packlo(c3.x, c3.y);

#pragma unroll
        for (int nt = 0; nt < 4; nt++) {
            float4 bf = Bs[buf][warpCol + nt * 8 + gid][tig];
            uint32_t bh0 = __float_as_uint(bf.x), bh1 = __float_as_uint(bf.y);
            uint32_t bl0 = __float_as_uint(bf.z), bl1 = __float_as_uint(bf.w);
#define MMA16(A0,A1,A2,A3,B0,B1)                                             \
            asm volatile(                                                     \
                "mma.sync.aligned.m16n8k16.row.col.f32.bf16.bf16.f32 "        \
                "{%0,%1,%2,%3}, {%4,%5,%6,%7}, {%8,%9}, {%0,%1,%2,%3};"       \
                : "+f"(acc[nt][0]), "+f"(acc[nt][1]),                         \
                  "+f"(acc[nt][2]), "+f"(acc[nt][3])                          \
                : "r"(A0), "r"(A1), "r"(A2), "r"(A3), "r"(B0), "r"(B1))
            MMA16(ah0, ah1, ah2, ah3, bh0, bh1);   // hi*hi
            MMA16(ah0, ah1, ah2, ah3, bl0, bl1);   // hi*lo
            MMA16(al0, al1, al2, al3, bh0, bh1);   // lo*hi
#undef MMA16
        }

        if (kc < 7) {
            Bs[buf ^ 1][scol][skk] = make_float4(__uint_as_float(packhi(w0, w1)),
                                                 __uint_as_float(packhi(w2, w3)),
                                                 __uint_as_float(packlo(w0, w1)),
                                                 __uint_as_float(packlo(w2, w3)));
            c0 = n0; c1 = n1; c2 = n2; c3 = n3;
        }
        __syncthreads();
    }

    // ---- store h (fp16) + fused att partial dots (blockIdx.y == head) ----
    int head = blockIdx.y;
    float s_r0 = 0.f, d_r0 = 0.f, s_r1 = 0.f, d_r1 = 0.f;
#pragma unroll
    for (int nt = 0; nt < 4; nt++) {
        int c = warpCol + nt * 8 + tig * 2;           // col within 64 (== within head)
        *(__half2*)&g_hh[(size_t)row0 * HO + colBase + c] =
            __floats2half2_rn(acc[nt][0], acc[nt][1]);
        *(__half2*)&g_hh[(size_t)row1 * HO + colBase + c] =
            __floats2half2_rn(acc[nt][2], acc[nt][3]);
        float as0 = att_src[head * OO + c], as1 = att_src[head * OO + c + 1];
        float ad0 = att_dst[head * OO + c], ad1 = att_dst[head * OO + c + 1];
        s_r0 += acc[nt][0] * as0 + acc[nt][1] * as1;
        d_r0 += acc[nt][0] * ad0 + acc[nt][1] * ad1;
        s_r1 += acc[nt][2] * as0 + acc[nt][3] * as1;
        d_r1 += acc[nt][2] * ad0 + acc[nt][3] * ad1;
    }
#pragma unroll
    for (int d = 1; d < 4; d <<= 1) {   // reduce over tig (lane bits 0..1)
        s_r0 += __shfl_xor_sync(0xffffffffu, s_r0, d);
        d_r0 += __shfl_xor_sync(0xffffffffu, d_r0, d);
        s_r1 += __shfl_xor_sync(0xffffffffu, s_r1, d);
        d_r1 += __shfl_xor_sync(0xffffffffu, d_r1, d);
    }
    if (tig == 0) {
        red[w][gid][0] = s_r0; red[w][gid][1] = d_r0;
        red[w][gid][2] = s_r1; red[w][gid][3] = d_r1;
    }
    __syncthreads();
    if (t < 64) {                        // one thread per block row
        int wq = t >> 4;
        int rr = t & 15;
        int g = rr & 7, half = rr >> 3;
        float s = red[wq][g][half * 2]     + red[wq + 4][g][half * 2];
        float d = red[wq][g][half * 2 + 1] + red[wq + 4][g][half * 2 + 1];
        int row = rowBase + wq * 16 + half * 8 + g;
        g_asrc[row * 4 + head] = s;
        g_adst[row * 4 + head] = d;
    }
}

// ---------------- fused segment-softmax + aggregation (no-max exp) ----------
__device__ __forceinline__ float lrelu(float a) {
    return fmaxf(a, 0.f) + 0.2f * fminf(a, 0.f);
}

__global__ __launch_bounds__(256) void agg_kernel(float* __restrict__ out,
                                                  const float* __restrict__ bias) {
    __shared__ float4 s_w[8][32];
    __shared__ int    s_idx[8][32];

    int gw = (blockIdx.x * blockDim.x + threadIdx.x) >> 5;   // 0..MM-1 exact
    int w = threadIdx.x >> 5;
    int lane = threadIdx.x & 31;
    int n = gw >> 2;
    int b = gw & 3;
    int beg = g_off[n], end = g_off[n + 1];

    float4 ad = *(const float4*)&g_adst[(b * NN + n) * 4];
    float4 ce = g_cedge;
    int myhead = lane >> 3;
    const __half* hbase = g_hh + (size_t)(b * NN) * HO + lane * 8;

    float S0 = 0.f, S1 = 0.f, S2 = 0.f, S3 = 0.f;   // per-lane partials
    float acc[8] = {0, 0, 0, 0, 0, 0, 0, 0};

    for (int c0 = beg; c0 < end; c0 += 32) {
        int i = c0 + lane;
        float p0 = 0.f, p1 = 0.f, p2 = 0.f, p3 = 0.f;
        int sidx = 0;
        if (i < end) {
            int2 e = g_cs[i];
            sidx = e.x;
            float ww = __int_as_float(e.y);
            float4 as = *(const float4*)&g_asrc[(b * NN + sidx) * 4];
            p0 = __expf(lrelu(as.x + ad.x + ww * ce.x));
            p1 = __expf(lrelu(as.y + ad.y + ww * ce.y));
            p2 = __expf(lrelu(as.z + ad.z + ww * ce.z));
            p3 = __expf(lrelu(as.w + ad.w + ww * ce.w));
            S0 += p0; S1 += p1; S2 += p2; S3 += p3;
        }
        s_idx[w][lane] = sidx;
        s_w[w][lane] = make_float4(p0, p1, p2, p3);
        __syncwarp();

        int cnt = min(32, end - c0);
#pragma unroll 8
        for (int j = 0; j < cnt; j++) {
            int sj = s_idx[w][j];
            float wj = ((const float*)&s_w[w][j])[myhead];
            int4 pk = *(const int4*)(hbase + (size_t)sj * HO);
            float2 f0 = __half22float2(*(__half2*)&pk.x);
            float2 f1 = __half22float2(*(__half2*)&pk.y);
            float2 f2 = __half22float2(*(__half2*)&pk.z);
            float2 f3 = __half22float2(*(__half2*)&pk.w);
            acc[0] = fmaf(wj, f0.x, acc[0]); acc[1] = fmaf(wj, f0.y, acc[1]);
            acc[2] = fmaf(wj, f1.x, acc[2]); acc[3] = fmaf(wj, f1.y, acc[3]);
            acc[4] = fmaf(wj, f2.x, acc[4]); acc[5] = fmaf(wj, f2.y, acc[5]);
            acc[6] = fmaf(wj, f3.x, acc[6]); acc[7] = fmaf(wj, f3.y, acc[7]);
        }
        __syncwarp();
    }

    // one warp-reduction of S per head, at the end only
#pragma unroll
    for (int d = 16; d; d >>= 1) {
        S0 += __shfl_xor_sync(0xffffffffu, S0, d);
        S1 += __shfl_xor_sync(0xffffffffu, S1, d);
        S2 += __shfl_xor_sync(0xffffffffu, S2, d);
        S3 += __shfl_xor_sync(0xffffffffu, S3, d);
    }
    float Sh = (myhead == 0) ? S0 : (myhead == 1) ? S1 : (myhead == 2) ? S2 : S3;
    float r = 1.f / fmaxf(Sh, 1e-16f);
#pragma unroll
    for (int k = 0; k < 8; k++) acc[k] *= r;

    // mean over heads: lanes l, l^8, l^16, l^24 hold same o, different h
#pragma unroll
    for (int k = 0; k < 8; k++) {
        float v = acc[k];
        v += __shfl_xor_sync(0xffffffffu, v, 8);
        v += __shfl_xor_sync(0xffffffffu, v, 16);
        acc[k] = v;
    }
    if (lane < 8) {
        float* op = out + ((size_t)b * NN + n) * OO + lane * 8;
#pragma unroll
        for (int k = 0; k < 8; k++)
            op[k] = acc[k] * 0.25f + bias[lane * 8 + k];
    }
}

// ---------------- launch ----------------------------------------------------
extern "C" void kernel_launch(void* const* d_in, const int* in_sizes, int n_in,
                              void* d_out, int out_size) {
    const float* x        = (const float*)d_in[0];
    const void*  ei       = d_in[1];
    const float* ea       = (const float*)d_in[2];
    const float* Wsrc     = (const float*)d_in[3];
    const float* att_src  = (const float*)d_in[4];
    const float* att_dst  = (const float*)d_in[5];
    const float* Wedge    = (const float*)d_in[6];
    const float* att_edge = (const float*)d_in[7];
    const float* bias     = (const float*)d_in[8];
    float* out = (float*)d_out;

    csr_kernel<<<CSRB, 256>>>((const int*)ei, ea, Wedge, att_edge);
    gemm_kernel<<<dim3(MM / 64, HO / 64), 256>>>(x, Wsrc, att_src, att_dst);
    agg_kernel<<<MM / 8, 256>>>(out, bias);
}

// round 12
// speedup vs baseline: 1.1178x; 1.1178x over previous
#include <cuda_runtime.h>
#include <cuda_fp16.h>
#include <cuda_bf16.h>
#include <cstdint>

#define NN 10000
#define BB 4
#define EE 160000
#define DD 128
#define HH 4
#define OO 64
#define HO 256            // H*O
#define MM (BB*NN)        // 40000 rows

// ---------------- scratch (device globals; no allocation allowed) ----------
__device__ __half g_hh[(size_t)MM * HO];   // projected features, fp16 [b*N+n][h*64+o]
__device__ float g_asrc[MM * HH];          // [b*N+n][h]
__device__ float g_adst[MM * HH];
__device__ float4 g_cedge;                 // c[h] = sum_o W_edge[h,o]*att_edge[h,o]
__device__ int   g_cnt[NN];                // zero-init; re-zeroed by scatter tail
__device__ int   g_off[NN + 1];
__device__ int   g_cur[NN];
__device__ int2  g_cs[EE];                 // packed (src, __float_as_int(ea)) per CSR slot

// ---------------- hist: per-block dtype detect + histogram + cedge ----------
__global__ __launch_bounds__(256) void hist_kernel(
    const int* __restrict__ ei, const float* __restrict__ W_edge,
    const float* __restrict__ att_edge) {
    __shared__ int sIs64;
    int tid = threadIdx.x;
    int e = blockIdx.x * 256 + tid;          // 0..EE-1 exactly
    if (tid == 0) {
        int z = 1;
        for (int i = 1; i < 64; i += 2)
            if (ei[i] != 0) z = 0;
        sIs64 = z;
    }
    __syncthreads();
    int d;
    if (sIs64) d = (int)((const long long*)ei)[(size_t)EE + e];
    else       d = ei[EE + e];
    d = min(max(d, 0), NN - 1);
    atomicAdd(&g_cnt[d], 1);

    if (blockIdx.x == 0 && tid < 128) {      // cedge (independent)
        int head = tid >> 5, lane = tid & 31;
        float cs = W_edge[head * OO + lane] * att_edge[head * OO + lane]
                 + W_edge[head * OO + lane + 32] * att_edge[head * OO + lane + 32];
#pragma unroll
        for (int dd = 16; dd; dd >>= 1) cs += __shfl_xor_sync(0xffffffffu, cs, dd);
        if (lane == 0) ((float*)&g_cedge)[head] = cs;
    }
}

// ---------------- exclusive scan of counts (single block) -------------------
__global__ void scan_kernel() {
    __shared__ int wsum[32];
    int t = threadIdx.x;
    int base = t * 10;
    int loc[10];
    int run = 0;
#pragma unroll
    for (int i = 0; i < 10; i++) {
        int idx = base + i;
        int c = (idx < NN) ? g_cnt[idx] : 0;
        loc[i] = run;
        run += c;
    }
    int lane = t & 31, wid = t >> 5;
    int inc = run;
#pragma unroll
    for (int d = 1; d < 32; d <<= 1) {
        int u = __shfl_up_sync(0xffffffffu, inc, d);
        if (lane >= d) inc += u;
    }
    if (lane == 31) wsum[wid] = inc;
    __syncthreads();
    if (wid == 0) {
        int wv = wsum[lane];
#pragma unroll
        for (int d = 1; d < 32; d <<= 1) {
            int u = __shfl_up_sync(0xffffffffu, wv, d);
            if (lane >= d) wv += u;
        }
        wsum[lane] = wv;
    }
    __syncthreads();
    int excl = inc - run + (wid ? wsum[wid - 1] : 0);
#pragma unroll
    for (int i = 0; i < 10; i++) {
        int idx = base + i;
        if (idx < NN) {
            int v = excl + loc[i];
            g_off[idx] = v;
            g_cur[idx] = v;
        }
    }
    if (t == 0) g_off[NN] = EE;
}

// ---------------- scatter + zero counters for the NEXT call -----------------
__global__ __launch_bounds__(256) void scatter_kernel(
    const int* __restrict__ ei, const float* __restrict__ ea) {
    __shared__ int sIs64;
    int tid = threadIdx.x;
    int e = blockIdx.x * 256 + tid;
    if (tid == 0) {
        int z = 1;
        for (int i = 1; i < 64; i += 2)
            if (ei[i] != 0) z = 0;
        sIs64 = z;
    }
    __syncthreads();
    int s, d;
    if (sIs64) {
        s = (int)((const long long*)ei)[e];
        d = (int)((const long long*)ei)[(size_t)EE + e];
    } else {
        s = ei[e];
        d = ei[EE + e];
    }
    s = min(max(s, 0), NN - 1);
    d = min(max(d, 0), NN - 1);
    int pos = atomicAdd(&g_cur[d], 1);
    g_cs[pos] = make_int2(s, __float_as_int(ea[e]));
    // scan has consumed g_cnt; zero it here for the next invocation
    if (e < NN) g_cnt[e] = 0;
}

// ---------------- bf16-split tensor-core GEMM + fused att epilogue ----------
// h = x @ W  (M=40000, K=128, N=256). Block tile 64x64; blockIdx.y == head.
__device__ __forceinline__ float bhi(float x) {          // bf16-truncated value
    return __uint_as_float(__float_as_uint(x) & 0xffff0000u);
}
__device__ __forceinline__ uint32_t packhi(float a, float b) {   // {a.hi16, b.hi16<<16}
    return __byte_perm(__float_as_uint(a), __float_as_uint(b), 0x7632);
}
__device__ __forceinline__ uint32_t packlo(float a, float b) {   // rn residuals
    uint32_t r;
    asm("cvt.rn.bf16x2.f32 %0, %1, %2;" : "=r"(r)
        : "f"(b - bhi(b)), "f"(a - bhi(a)));             // first src -> high half
    return r;
}

__global__ __launch_bounds__(256) void gemm_kernel(
    const float* __restrict__ A, const float* __restrict__ W,
    const float* __restrict__ att_src, const float* __restrict__ att_dst) {
    __shared__ float4 Bs[2][64][5];      // [buf][col][tig] = (bh0,bh1,bl0,bl1), pad 5
    __shared__ float red[8][8][4];

    int t = threadIdx.x;
    int w = t >> 5, lane = t & 31, gid = lane >> 2, tig = lane & 3;
    int rowBase = blockIdx.x * 64, colBase = blockIdx.y * 64;
    int warpRow = (w & 3) * 16, warpCol = (w >> 2) * 32;

    float acc[4][4];
#pragma unroll
    for (int i = 0; i < 4; i++)
#pragma unroll
        for (int j = 0; j < 4; j++) acc[i][j] = 0.f;

    int row0 = rowBase + warpRow + gid;
    int row1 = row0 + 8;
    const float* Ap0 = A + (size_t)row0 * DD + 2 * tig;
    const float* Ap1 = A + (size_t)row1 * DD + 2 * tig;

    int scol = t & 63, skk = t >> 6;                 // B stage: col, tig-slot
    const float* Wp = W + colBase + scol + (size_t)(2 * skk) * HO;

    float2 c0 = *(const float2*)(Ap0);
    float2 c1 = *(const float2*)(Ap0 + 8);
    float2 c2 = *(const float2*)(Ap1);
    float2 c3 = *(const float2*)(Ap1 + 8);
    {
        float w0 = Wp[0], w1 = Wp[HO], w2 = Wp[8 * HO], w3 = Wp[9 * HO];
        Bs[0][scol][skk] = make_float4(__uint_as_float(packhi(w0, w1)),
                                       __uint_as_float(packhi(w2, w3)),
                                       __uint_as_float(packlo(w0, w1)),
                                       __uint_as_float(packlo(w2, w3)));
    }
    __syncthreads();

#pragma unroll
    for (int kc = 0; kc < 8; kc++) {
        int buf = kc & 1;
        float2 n0, n1, n2, n3;
        float w0, w1, w2, w3;
        if (kc < 7) {                                // prefetch next A + W
            int base = (kc + 1) * 16;
            n0 = *(const float2*)(Ap0 + base);
            n1 = *(const float2*)(Ap0 + base + 8);
            n2 = *(const float2*)(Ap1 + base);
            n3 = *(const float2*)(Ap1 + base + 8);
            const float* wp = Wp + (size_t)base * HO;
            w0 = wp[0]; w1 = wp[HO]; w2 = wp[8 * HO]; w3 = wp[9 * HO];
        }

        uint32_t ah0 = packhi(c0.x, c0.y), al0 = packlo(c0.x, c0.y);
        uint32_t ah1 = packhi(c2.x, c2.y), al1 = packlo(c2.x, c2.y);
        uint32_t ah2 = packhi(c1.x, c1.y), al2 = packlo(c1.x, c1.y);
        uint32_t ah3 = packhi(c3.x, c3.y), al3 = packlo(c3.x, c3.y);

#pragma unroll
        for (int nt = 0; nt < 4; nt++) {
            float4 bf = Bs[buf][warpCol + nt * 8 + gid][tig];
            uint32_t bh0 = __float_as_uint(bf.x), bh1 = __float_as_uint(bf.y);
            uint32_t bl0 = __float_as_uint(bf.z), bl1 = __float_as_uint(bf.w);
#define MMA16(A0,A1,A2,A3,B0,B1)                                             \
            asm volatile(                                                     \
                "mma.sync.aligned.m16n8k16.row.col.f32.bf16.bf16.f32 "        \
                "{%0,%1,%2,%3}, {%4,%5,%6,%7}, {%8,%9}, {%0,%1,%2,%3};"       \
                : "+f"(acc[nt][0]), "+f"(acc[nt][1]),                         \
                  "+f"(acc[nt][2]), "+f"(acc[nt][3])                          \
                : "r"(A0), "r"(A1), "r"(A2), "r"(A3), "r"(B0), "r"(B1))
            MMA16(ah0, ah1, ah2, ah3, bh0, bh1);   // hi*hi
            MMA16(ah0, ah1, ah2, ah3, bl0, bl1);   // hi*lo
            MMA16(al0, al1, al2, al3, bh0, bh1);   // lo*hi
#undef MMA16
        }

        if (kc < 7) {
            Bs[buf ^ 1][scol][skk] = make_float4(__uint_as_float(packhi(w0, w1)),
                                                 __uint_as_float(packhi(w2, w3)),
                                                 __uint_as_float(packlo(w0, w1)),
                                                 __uint_as_float(packlo(w2, w3)));
            c0 = n0; c1 = n1; c2 = n2; c3 = n3;
        }
        __syncthreads();
    }

    // ---- store h (fp16) + fused att partial dots (blockIdx.y == head) ----
    int head = blockIdx.y;
    float s_r0 = 0.f, d_r0 = 0.f, s_r1 = 0.f, d_r1 = 0.f;
#pragma unroll
    for (int nt = 0; nt < 4; nt++) {
        int c = warpCol + nt * 8 + tig * 2;           // col within 64 (== within head)
        *(__half2*)&g_hh[(size_t)row0 * HO + colBase + c] =
            __floats2half2_rn(acc[nt][0], acc[nt][1]);
        *(__half2*)&g_hh[(size_t)row1 * HO + colBase + c] =
            __floats2half2_rn(acc[nt][2], acc[nt][3]);
        float as0 = att_src[head * OO + c], as1 = att_src[head * OO + c + 1];
        float ad0 = att_dst[head * OO + c], ad1 = att_dst[head * OO + c + 1];
        s_r0 += acc[nt][0] * as0 + acc[nt][1] * as1;
        d_r0 += acc[nt][0] * ad0 + acc[nt][1] * ad1;
        s_r1 += acc[nt][2] * as0 + acc[nt][3] * as1;
        d_r1 += acc[nt][2] * ad0 + acc[nt][3] * ad1;
    }
#pragma unroll
    for (int d = 1; d < 4; d <<= 1) {   // reduce over tig (lane bits 0..1)
        s_r0 += __shfl_xor_sync(0xffffffffu, s_r0, d);
        d_r0 += __shfl_xor_sync(0xffffffffu, d_r0, d);
        s_r1 += __shfl_xor_sync(0xffffffffu, s_r1, d);
        d_r1 += __shfl_xor_sync(0xffffffffu, d_r1, d);
    }
    if (tig == 0) {
        red[w][gid][0] = s_r0; red[w][gid][1] = d_r0;
        red[w][gid][2] = s_r1; red[w][gid][3] = d_r1;
    }
    __syncthreads();
    if (t < 64) {                        // one thread per block row
        int wq = t >> 4;
        int rr = t & 15;
        int g = rr & 7, half = rr >> 3;
        float s = red[wq][g][half * 2]     + red[wq + 4][g][half * 2];
        float d = red[wq][g][half * 2 + 1] + red[wq + 4][g][half * 2 + 1];
        int row = rowBase + wq * 16 + half * 8 + g;
        g_asrc[row * 4 + head] = s;
        g_adst[row * 4 + head] = d;
    }
}

// ---------------- fused segment-softmax + aggregation (no-max exp) ----------
__device__ __forceinline__ float lrelu(float a) {
    return fmaxf(a, 0.f) + 0.2f * fminf(a, 0.f);
}

__global__ __launch_bounds__(256) void agg_kernel(float* __restrict__ out,
                                                  const float* __restrict__ bias) {
    __shared__ float4 s_w[8][32];
    __shared__ int    s_idx[8][32];

    int gw = (blockIdx.x * blockDim.x + threadIdx.x) >> 5;   // 0..MM-1 exact
    int w = threadIdx.x >> 5;
    int lane = threadIdx.x & 31;
    int n = gw >> 2;
    int b = gw & 3;
    int beg = g_off[n], end = g_off[n + 1];

    float4 ad = *(const float4*)&g_adst[(b * NN + n) * 4];
    float4 ce = g_cedge;
    int myhead = lane >> 3;
    const __half* hbase = g_hh + (size_t)(b * NN) * HO + lane * 8;

    float S0 = 0.f, S1 = 0.f, S2 = 0.f, S3 = 0.f;   // per-lane partials
    float acc[8] = {0, 0, 0, 0, 0, 0, 0, 0};

    for (int c0 = beg; c0 < end; c0 += 32) {
        int i = c0 + lane;
        float p0 = 0.f, p1 = 0.f, p2 = 0.f, p3 = 0.f;
        int sidx = 0;
        if (i < end) {
            int2 e = g_cs[i];
            sidx = e.x;
            float ww = __int_as_float(e.y);
            float4 as = *(const float4*)&g_asrc[(b * NN + sidx) * 4];
            p0 = __expf(lrelu(as.x + ad.x + ww * ce.x));
            p1 = __expf(lrelu(as.y + ad.y + ww * ce.y));
            p2 = __expf(lrelu(as.z + ad.z + ww * ce.z));
            p3 = __expf(lrelu(as.w + ad.w + ww * ce.w));
            S0 += p0; S1 += p1; S2 += p2; S3 += p3;
        }
        s_idx[w][lane] = sidx;
        s_w[w][lane] = make_float4(p0, p1, p2, p3);
        __syncwarp();

        int cnt = min(32, end - c0);
#pragma unroll 8
        for (int j = 0; j < cnt; j++) {
            int sj = s_idx[w][j];
            float wj = ((const float*)&s_w[w][j])[myhead];
            int4 pk = *(const int4*)(hbase + (size_t)sj * HO);
            float2 f0 = __half22float2(*(__half2*)&pk.x);
            float2 f1 = __half22float2(*(__half2*)&pk.y);
            float2 f2 = __half22float2(*(__half2*)&pk.z);
            float2 f3 = __half22float2(*(__half2*)&pk.w);
            acc[0] = fmaf(wj, f0.x, acc[0]); acc[1] = fmaf(wj, f0.y, acc[1]);
            acc[2] = fmaf(wj, f1.x, acc[2]); acc[3] = fmaf(wj, f1.y, acc[3]);
            acc[4] = fmaf(wj, f2.x, acc[4]); acc[5] = fmaf(wj, f2.y, acc[5]);
            acc[6] = fmaf(wj, f3.x, acc[6]); acc[7] = fmaf(wj, f3.y, acc[7]);
        }
        __syncwarp();
    }

    // one warp-reduction of S per head, at the end only
#pragma unroll
    for (int d = 16; d; d >>= 1) {
        S0 += __shfl_xor_sync(0xffffffffu, S0, d);
        S1 += __shfl_xor_sync(0xffffffffu, S1, d);
        S2 += __shfl_xor_sync(0xffffffffu, S2, d);
        S3 += __shfl_xor_sync(0xffffffffu, S3, d);
    }
    float Sh = (myhead == 0) ? S0 : (myhead == 1) ? S1 : (myhead == 2) ? S2 : S3;
    float r = 1.f / fmaxf(Sh, 1e-16f);
#pragma unroll
    for (int k = 0; k < 8; k++) acc[k] *= r;

    // mean over heads: lanes l, l^8, l^16, l^24 hold same o, different h
#pragma unroll
    for (int k = 0; k < 8; k++) {
        float v = acc[k];
        v += __shfl_xor_sync(0xffffffffu, v, 8);
        v += __shfl_xor_sync(0xffffffffu, v, 16);
        acc[k] = v;
    }
    if (lane < 8) {
        float* op = out + ((size_t)b * NN + n) * OO + lane * 8;
#pragma unroll
        for (int k = 0; k < 8; k++)
            op[k] = acc[k] * 0.25f + bias[lane * 8 + k];
    }
}

// ---------------- launch ----------------------------------------------------
extern "C" void kernel_launch(void* const* d_in, const int* in_sizes, int n_in,
                              void* d_out, int out_size) {
    const float* x        = (const float*)d_in[0];
    const void*  ei       = d_in[1];
    const float* ea       = (const float*)d_in[2];
    const float* Wsrc     = (const float*)d_in[3];
    const float* att_src  = (const float*)d_in[4];
    const float* att_dst  = (const float*)d_in[5];
    const float* Wedge    = (const float*)d_in[6];
    const float* att_edge = (const float*)d_in[7];
    const float* bias     = (const float*)d_in[8];
    float* out = (float*)d_out;

    static cudaStream_t s_csr = nullptr;
    static cudaEvent_t  ev_fork = nullptr, ev_join = nullptr;
    if (s_csr == nullptr) {
        cudaStreamCreateWithFlags(&s_csr, cudaStreamNonBlocking);
        cudaEventCreateWithFlags(&ev_fork, cudaEventDisableTiming);
        cudaEventCreateWithFlags(&ev_join, cudaEventDisableTiming);
    }

    // fork: CSR chain on side stream, GEMM on main stream, join before agg
    cudaEventRecord(ev_fork, 0);
    cudaStreamWaitEvent(s_csr, ev_fork, 0);

    hist_kernel<<<EE / 256, 256, 0, s_csr>>>((const int*)ei, Wedge, att_edge);
    scan_kernel<<<1, 1024, 0, s_csr>>>();
    scatter_kernel<<<EE / 256, 256, 0, s_csr>>>((const int*)ei, ea);
    cudaEventRecord(ev_join, s_csr);

    gemm_kernel<<<dim3(MM / 64, HO / 64), 256>>>(x, Wsrc, att_src, att_dst);

    cudaStreamWaitEvent(0, ev_join, 0);
    agg_kernel<<<MM / 8, 256>>>(out, bias);
}

// round 13
// speedup vs baseline: 1.2126x; 1.0848x over previous
#include <cuda_runtime.h>
#include <cuda_fp16.h>
#include <cuda_bf16.h>
#include <cstdint>

#define NN 10000
#define BB 4
#define EE 160000
#define DD 128
#define HH 4
#define OO 64
#define HO 256            // H*O
#define MM (BB*NN)        // 40000 rows

// ---------------- scratch (device globals; no allocation allowed) ----------
__device__ __half g_hh[(size_t)MM * HO];   // projected features, fp16 [b*N+n][h*64+o]
__device__ float g_asrc[MM * HH];          // [b*N+n][h]
__device__ float g_adst[MM * HH];
__device__ float4 g_cedge;                 // c[h] = sum_o W_edge[h,o]*att_edge[h,o]
__device__ int   g_cnt[NN];                // zero-init; re-zeroed by scatter tail
__device__ int   g_off[NN + 1];
__device__ int   g_cur[NN];
__device__ int2  g_cs[EE];                 // packed (src, __float_as_int(ea)) per CSR slot

// ---------------- hist: per-block dtype detect + histogram + cedge ----------
__global__ __launch_bounds__(256) void hist_kernel(
    const int* __restrict__ ei, const float* __restrict__ W_edge,
    const float* __restrict__ att_edge) {
    __shared__ int sIs64;
    int tid = threadIdx.x;
    int e = blockIdx.x * 256 + tid;          // 0..EE-1 exactly
    if (tid == 0) {
        int z = 1;
        for (int i = 1; i < 64; i += 2)
            if (ei[i] != 0) z = 0;
        sIs64 = z;
    }
    __syncthreads();
    int d;
    if (sIs64) d = (int)((const long long*)ei)[(size_t)EE + e];
    else       d = ei[EE + e];
    d = min(max(d, 0), NN - 1);
    atomicAdd(&g_cnt[d], 1);

    if (blockIdx.x == 0 && tid < 128) {      // cedge (independent)
        int head = tid >> 5, lane = tid & 31;
        float cs = W_edge[head * OO + lane] * att_edge[head * OO + lane]
                 + W_edge[head * OO + lane + 32] * att_edge[head * OO + lane + 32];
#pragma unroll
        for (int dd = 16; dd; dd >>= 1) cs += __shfl_xor_sync(0xffffffffu, cs, dd);
        if (lane == 0) ((float*)&g_cedge)[head] = cs;
    }
}

// ---------------- exclusive scan of counts (single block) -------------------
__global__ void scan_kernel() {
    __shared__ int wsum[32];
    int t = threadIdx.x;
    int base = t * 10;
    int loc[10];
    int run = 0;
#pragma unroll
    for (int i = 0; i < 10; i++) {
        int idx = base + i;
        int c = (idx < NN) ? g_cnt[idx] : 0;
        loc[i] = run;
        run += c;
    }
    int lane = t & 31, wid = t >> 5;
    int inc = run;
#pragma unroll
    for (int d = 1; d < 32; d <<= 1) {
        int u = __shfl_up_sync(0xffffffffu, inc, d);
        if (lane >= d) inc += u;
    }
    if (lane == 31) wsum[wid] = inc;
    __syncthreads();
    if (wid == 0) {
        int wv = wsum[lane];
#pragma unroll
        for (int d = 1; d < 32; d <<= 1) {
            int u = __shfl_up_sync(0xffffffffu, wv, d);
            if (lane >= d) wv += u;
        }
        wsum[lane] = wv;
    }
    __syncthreads();
    int excl = inc - run + (wid ? wsum[wid - 1] : 0);
#pragma unroll
    for (int i = 0; i < 10; i++) {
        int idx = base + i;
        if (idx < NN) {
            int v = excl + loc[i];
            g_off[idx] = v;
            g_cur[idx] = v;
        }
    }
    if (t == 0) g_off[NN] = EE;
}

// ---------------- scatter + zero counters for the NEXT call -----------------
__global__ __launch_bounds__(256) void scatter_kernel(
    const int* __restrict__ ei, const float* __restrict__ ea) {
    __shared__ int sIs64;
    int tid = threadIdx.x;
    int e = blockIdx.x * 256 + tid;
    if (tid == 0) {
        int z = 1;
        for (int i = 1; i < 64; i += 2)
            if (ei[i] != 0) z = 0;
        sIs64 = z;
    }
    __syncthreads();
    int s, d;
    if (sIs64) {
        s = (int)((const long long*)ei)[e];
        d = (int)((const long long*)ei)[(size_t)EE + e];
    } else {
        s = ei[e];
        d = ei[EE + e];
    }
    s = min(max(s, 0), NN - 1);
    d = min(max(d, 0), NN - 1);
    int pos = atomicAdd(&g_cur[d], 1);
    g_cs[pos] = make_int2(s, __float_as_int(ea[e]));
    // scan has consumed g_cnt; zero it here for the next invocation
    if (e < NN) g_cnt[e] = 0;
}

// ---------------- bf16-split tensor-core GEMM + fused att epilogue ----------
// h = x @ W  (M=40000, K=128, N=256). Block tile 64x64; blockIdx.y == head.
// A tile staged ONCE into padded smem with coalesced LDG.128 (pitch 136 floats
// -> conflict-free fragment LDS.64); B double-buffered as packed fragments.
__device__ __forceinline__ float bhi(float x) {          // bf16-truncated value
    return __uint_as_float(__float_as_uint(x) & 0xffff0000u);
}
__device__ __forceinline__ uint32_t packhi(float a, float b) {   // {a.hi16, b.hi16<<16}
    return __byte_perm(__float_as_uint(a), __float_as_uint(b), 0x7632);
}
__device__ __forceinline__ uint32_t packlo(float a, float b) {   // rn residuals
    uint32_t r;
    asm("cvt.rn.bf16x2.f32 %0, %1, %2;" : "=r"(r)
        : "f"(b - bhi(b)), "f"(a - bhi(a)));             // first src -> high half
    return r;
}

__global__ __launch_bounds__(256) void gemm_kernel(
    const float* __restrict__ A, const float* __restrict__ W,
    const float* __restrict__ att_src, const float* __restrict__ att_dst) {
    __shared__ float As[64][136];        // 64 rows x 128 k, pitch 136 (bank-offset 8)
    __shared__ float4 Bs[2][64][5];      // [buf][col][tig] = (bh0,bh1,bl0,bl1), pad 5
    __shared__ float red[8][8][4];

    int t = threadIdx.x;
    int w = t >> 5, lane = t & 31, gid = lane >> 2, tig = lane & 3;
    int rowBase = blockIdx.x * 64, colBase = blockIdx.y * 64;
    int warpRow = (w & 3) * 16, warpCol = (w >> 2) * 32;

    // stage full A tile, coalesced: warp instruction = 512 contiguous bytes
    {
        const float* Ab = A + (size_t)rowBase * DD;
#pragma unroll
        for (int p = 0; p < 8; p++) {
            int idx = p * 1024 + t * 4;
            float4 v = *(const float4*)(Ab + idx);
            *(float4*)&As[idx >> 7][idx & 127] = v;
        }
    }

    int scol = t & 63, skk = t >> 6;                 // B stage: col, tig-slot
    const float* Wp = W + colBase + scol + (size_t)(2 * skk) * HO;
    {
        float w0 = Wp[0], w1 = Wp[HO], w2 = Wp[8 * HO], w3 = Wp[9 * HO];
        Bs[0][scol][skk] = make_float4(__uint_as_float(packhi(w0, w1)),
                                       __uint_as_float(packhi(w2, w3)),
                                       __uint_as_float(packlo(w0, w1)),
                                       __uint_as_float(packlo(w2, w3)));
    }
    __syncthreads();

    float acc[4][4];
#pragma unroll
    for (int i = 0; i < 4; i++)
#pragma unroll
        for (int j = 0; j < 4; j++) acc[i][j] = 0.f;

    int lrow0 = warpRow + gid;           // local rows in As
    int lrow1 = lrow0 + 8;

#pragma unroll
    for (int kc = 0; kc < 8; kc++) {
        int buf = kc & 1;
        float w0, w1, w2, w3;
        if (kc < 7) {                                // prefetch next W chunk
            const float* wp = Wp + (size_t)((kc + 1) * 16) * HO;
            w0 = wp[0]; w1 = wp[HO]; w2 = wp[8 * HO]; w3 = wp[9 * HO];
        }

        // A fragments from smem (conflict-free LDS.64)
        float2 c0 = *(const float2*)&As[lrow0][kc * 16 + 2 * tig];
        float2 c1 = *(const float2*)&As[lrow0][kc * 16 + 8 + 2 * tig];
        float2 c2 = *(const float2*)&As[lrow1][kc * 16 + 2 * tig];
        float2 c3 = *(const float2*)&As[lrow1][kc * 16 + 8 + 2 * tig];

        uint32_t ah0 = packhi(c0.x, c0.y), al0 = packlo(c0.x, c0.y);
        uint32_t ah1 = packhi(c2.x, c2.y), al1 = packlo(c2.x, c2.y);
        uint32_t ah2 = packhi(c1.x, c1.y), al2 = packlo(c1.x, c1.y);
        uint32_t ah3 = packhi(c3.x, c3.y), al3 = packlo(c3.x, c3.y);

#pragma unroll
        for (int nt = 0; nt < 4; nt++) {
            float4 bf = Bs[buf][warpCol + nt * 8 + gid][tig];
            uint32_t bh0 = __float_as_uint(bf.x), bh1 = __float_as_uint(bf.y);
            uint32_t bl0 = __float_as_uint(bf.z), bl1 = __float_as_uint(bf.w);
#define MMA16(A0,A1,A2,A3,B0,B1)                                             \
            asm volatile(                                                     \
                "mma.sync.aligned.m16n8k16.row.col.f32.bf16.bf16.f32 "        \
                "{%0,%1,%2,%3}, {%4,%5,%6,%7}, {%8,%9}, {%0,%1,%2,%3};"       \
                : "+f"(acc[nt][0]), "+f"(acc[nt][1]),                         \
                  "+f"(acc[nt][2]), "+f"(acc[nt][3])                          \
                : "r"(A0), "r"(A1), "r"(A2), "r"(A3), "r"(B0), "r"(B1))
            MMA16(ah0, ah1, ah2, ah3, bh0, bh1);   // hi*hi
            MMA16(ah0, ah1, ah2, ah3, bl0, bl1);   // hi*lo
            MMA16(al0, al1, al2, al3, bh0, bh1);   // lo*hi
#undef MMA16
        }

        if (kc < 7) {                                // stage next B into buf^1
            Bs[buf ^ 1][scol][skk] = make_float4(__uint_as_float(packhi(w0, w1)),
                                                 __uint_as_float(packhi(w2, w3)),
                                                 __uint_as_float(packlo(w0, w1)),
                                                 __uint_as_float(packlo(w2, w3)));
        }
        __syncthreads();
    }

    // ---- store h (fp16) + fused att partial dots (blockIdx.y == head) ----
    int head = blockIdx.y;
    int row0 = rowBase + lrow0;
    int row1 = rowBase + lrow1;
    float s_r0 = 0.f, d_r0 = 0.f, s_r1 = 0.f, d_r1 = 0.f;
#pragma unroll
    for (int nt = 0; nt < 4; nt++) {
        int c = warpCol + nt * 8 + tig * 2;           // col within 64 (== within head)
        *(__half2*)&g_hh[(size_t)row0 * HO + colBase + c] =
            __floats2half2_rn(acc[nt][0], acc[nt][1]);
        *(__half2*)&g_hh[(size_t)row1 * HO + colBase + c] =
            __floats2half2_rn(acc[nt][2], acc[nt][3]);
        float as0 = att_src[head * OO + c], as1 = att_src[head * OO + c + 1];
        float ad0 = att_dst[head * OO + c], ad1 = att_dst[head * OO + c + 1];
        s_r0 += acc[nt][0] * as0 + acc[nt][1] * as1;
        d_r0 += acc[nt][0] * ad0 + acc[nt][1] * ad1;
        s_r1 += acc[nt][2] * as0 + acc[nt][3] * as1;
        d_r1 += acc[nt][2] * ad0 + acc[nt][3] * ad1;
    }
#pragma unroll
    for (int d = 1; d < 4; d <<= 1) {   // reduce over tig (lane bits 0..1)
        s_r0 += __shfl_xor_sync(0xffffffffu, s_r0, d);
        d_r0 += __shfl_xor_sync(0xffffffffu, d_r0, d);
        s_r1 += __shfl_xor_sync(0xffffffffu, s_r1, d);
        d_r1 += __shfl_xor_sync(0xffffffffu, d_r1, d);
    }
    if (tig == 0) {
        red[w][gid][0] = s_r0; red[w][gid][1] = d_r0;
        red[w][gid][2] = s_r1; red[w][gid][3] = d_r1;
    }
    __syncthreads();
    if (t < 64) {                        // one thread per block row
        int wq = t >> 4;
        int rr = t & 15;
        int g = rr & 7, half = rr >> 3;
        float s = red[wq][g][half * 2]     + red[wq + 4][g][half * 2];
        float d = red[wq][g][half * 2 + 1] + red[wq + 4][g][half * 2 + 1];
        int row = rowBase + wq * 16 + half * 8 + g;
        g_asrc[row * 4 + head] = s;
        g_adst[row * 4 + head] = d;
    }
}

// ---------------- fused segment-softmax + aggregation (no-max exp) ----------
__device__ __forceinline__ float lrelu(float a) {
    return fmaxf(a, 0.f) + 0.2f * fminf(a, 0.f);
}

__global__ __launch_bounds__(256) void agg_kernel(float* __restrict__ out,
                                                  const float* __restrict__ bias) {
    __shared__ float4 s_w[8][32];
    __shared__ int    s_idx[8][32];

    int gw = (blockIdx.x * blockDim.x + threadIdx.x) >> 5;   // 0..MM-1 exact
    int w = threadIdx.x >> 5;
    int lane = threadIdx.x & 31;
    int n = gw >> 2;
    int b = gw & 3;
    int beg = g_off[n], end = g_off[n + 1];

    float4 ad = *(const float4*)&g_adst[(b * NN + n) * 4];
    float4 ce = g_cedge;
    int myhead = lane >> 3;
    const __half* hbase = g_hh + (size_t)(b * NN) * HO + lane * 8;

    float S0 = 0.f, S1 = 0.f, S2 = 0.f, S3 = 0.f;   // per-lane partials
    float acc[8] = {0, 0, 0, 0, 0, 0, 0, 0};

    for (int c0 = beg; c0 < end; c0 += 32) {
        int i = c0 + lane;
        float p0 = 0.f, p1 = 0.f, p2 = 0.f, p3 = 0.f;
        int sidx = 0;
        if (i < end) {
            int2 e = g_cs[i];
            sidx = e.x;
            float ww = __int_as_float(e.y);
            float4 as = *(const float4*)&g_asrc[(b * NN + sidx) * 4];
            p0 = __expf(lrelu(as.x + ad.x + ww * ce.x));
            p1 = __expf(lrelu(as.y + ad.y + ww * ce.y));
            p2 = __expf(lrelu(as.z + ad.z + ww * ce.z));
            p3 = __expf(lrelu(as.w + ad.w + ww * ce.w));
            S0 += p0; S1 += p1; S2 += p2; S3 += p3;
        }
        s_idx[w][lane] = sidx;
        s_w[w][lane] = make_float4(p0, p1, p2, p3);
        __syncwarp();

        int cnt = min(32, end - c0);
#pragma unroll 8
        for (int j = 0; j < cnt; j++) {
            int sj = s_idx[w][j];
            float wj = ((const float*)&s_w[w][j])[myhead];
            int4 pk = *(const int4*)(hbase + (size_t)sj * HO);
            float2 f0 = __half22float2(*(__half2*)&pk.x);
            float2 f1 = __half22float2(*(__half2*)&pk.y);
            float2 f2 = __half22float2(*(__half2*)&pk.z);
            float2 f3 = __half22float2(*(__half2*)&pk.w);
            acc[0] = fmaf(wj, f0.x, acc[0]); acc[1] = fmaf(wj, f0.y, acc[1]);
            acc[2] = fmaf(wj, f1.x, acc[2]); acc[3] = fmaf(wj, f1.y, acc[3]);
            acc[4] = fmaf(wj, f2.x, acc[4]); acc[5] = fmaf(wj, f2.y, acc[5]);
            acc[6] = fmaf(wj, f3.x, acc[6]); acc[7] = fmaf(wj, f3.y, acc[7]);
        }
        __syncwarp();
    }

    // one warp-reduction of S per head, at the end only
#pragma unroll
    for (int d = 16; d; d >>= 1) {
        S0 += __shfl_xor_sync(0xffffffffu, S0, d);
        S1 += __shfl_xor_sync(0xffffffffu, S1, d);
        S2 += __shfl_xor_sync(0xffffffffu, S2, d);
        S3 += __shfl_xor_sync(0xffffffffu, S3, d);
    }
    float Sh = (myhead == 0) ? S0 : (myhead == 1) ? S1 : (myhead == 2) ? S2 : S3;
    float r = 1.f / fmaxf(Sh, 1e-16f);
#pragma unroll
    for (int k = 0; k < 8; k++) acc[k] *= r;

    // mean over heads: lanes l, l^8, l^16, l^24 hold same o, different h
#pragma unroll
    for (int k = 0; k < 8; k++) {
        float v = acc[k];
        v += __shfl_xor_sync(0xffffffffu, v, 8);
        v += __shfl_xor_sync(0xffffffffu, v, 16);
        acc[k] = v;
    }
    if (lane < 8) {
        float* op = out + ((size_t)b * NN + n) * OO + lane * 8;
#pragma unroll
        for (int k = 0; k < 8; k++)
            op[k] = acc[k] * 0.25f + bias[lane * 8 + k];
    }
}

// ---------------- launch ----------------------------------------------------
extern "C" void kernel_launch(void* const* d_in, const int* in_sizes, int n_in,
                              void* d_out, int out_size) {
    const float* x        = (const float*)d_in[0];
    const void*  ei       = d_in[1];
    const float* ea       = (const float*)d_in[2];
    const float* Wsrc     = (const float*)d_in[3];
    const float* att_src  = (const float*)d_in[4];
    const float* att_dst  = (const float*)d_in[5];
    const float* Wedge    = (const float*)d_in[6];
    const float* att_edge = (const float*)d_in[7];
    const float* bias     = (const float*)d_in[8];
    float* out = (float*)d_out;

    static cudaStream_t s_csr = nullptr;
    static cudaEvent_t  ev_fork = nullptr, ev_join = nullptr;
    if (s_csr == nullptr) {
        cudaStreamCreateWithFlags(&s_csr, cudaStreamNonBlocking);
        cudaEventCreateWithFlags(&ev_fork, cudaEventDisableTiming);
        cudaEventCreateWithFlags(&ev_join, cudaEventDisableTiming);
    }

    // fork: CSR chain on side stream, GEMM on main stream, join before agg
    cudaEventRecord(ev_fork, 0);
    cudaStreamWaitEvent(s_csr, ev_fork, 0);

    hist_kernel<<<EE / 256, 256, 0, s_csr>>>((const int*)ei, Wedge, att_edge);
    scan_kernel<<<1, 1024, 0, s_csr>>>();
    scatter_kernel<<<EE / 256, 256, 0, s_csr>>>((const int*)ei, ea);
    cudaEventRecord(ev_join, s_csr);

    gemm_kernel<<<dim3(MM / 64, HO / 64), 256>>>(x, Wsrc, att_src, att_dst);

    cudaStreamWaitEvent(0, ev_join, 0);
    agg_kernel<<<MM / 8, 256>>>(out, bias);
}

// round 14
// speedup vs baseline: 1.2602x; 1.0392x over previous
#include <cuda_runtime.h>
#include <cuda_fp16.h>
#include <cuda_bf16.h>
#include <cstdint>

#define NN 10000
#define BB 4
#define EE 160000
#define DD 128
#define HH 4
#define OO 64
#define HO 256            // H*O
#define MM (BB*NN)        // 40000 rows

// ---------------- scratch (device globals; no allocation allowed) ----------
__device__ __half g_hh[(size_t)MM * HO];   // projected features, fp16 [b*N+n][h*64+o]
__device__ float g_asrc[MM * HH];          // [b*N+n][h]
__device__ float g_adst[MM * HH];
__device__ float4 g_cedge;                 // c[h] = sum_o W_edge[h,o]*att_edge[h,o]
__device__ int   g_cnt[NN];                // zero-init; re-zeroed by scatter tail
__device__ int   g_off[NN + 1];
__device__ int   g_cur[NN];
__device__ int2  g_cs[EE];                 // packed (src, __float_as_int(ea)) per CSR slot

// ---------------- hist: per-block dtype detect + histogram + cedge ----------
__global__ __launch_bounds__(256) void hist_kernel(
    const int* __restrict__ ei, const float* __restrict__ W_edge,
    const float* __restrict__ att_edge) {
    __shared__ int sIs64;
    int tid = threadIdx.x;
    int e = blockIdx.x * 256 + tid;          // 0..EE-1 exactly
    if (tid == 0) {
        int z = 1;
        for (int i = 1; i < 64; i += 2)
            if (ei[i] != 0) z = 0;
        sIs64 = z;
    }
    __syncthreads();
    int d;
    if (sIs64) d = (int)((const long long*)ei)[(size_t)EE + e];
    else       d = ei[EE + e];
    d = min(max(d, 0), NN - 1);
    atomicAdd(&g_cnt[d], 1);

    if (blockIdx.x == 0 && tid < 128) {      // cedge (independent)
        int head = tid >> 5, lane = tid & 31;
        float cs = W_edge[head * OO + lane] * att_edge[head * OO + lane]
                 + W_edge[head * OO + lane + 32] * att_edge[head * OO + lane + 32];
#pragma unroll
        for (int dd = 16; dd; dd >>= 1) cs += __shfl_xor_sync(0xffffffffu, cs, dd);
        if (lane == 0) ((float*)&g_cedge)[head] = cs;
    }
}

// ---------------- exclusive scan of counts (single block) -------------------
__global__ void scan_kernel() {
    __shared__ int wsum[32];
    int t = threadIdx.x;
    int base = t * 10;
    int loc[10];
    int run = 0;
#pragma unroll
    for (int i = 0; i < 10; i++) {
        int idx = base + i;
        int c = (idx < NN) ? g_cnt[idx] : 0;
        loc[i] = run;
        run += c;
    }
    int lane = t & 31, wid = t >> 5;
    int inc = run;
#pragma unroll
    for (int d = 1; d < 32; d <<= 1) {
        int u = __shfl_up_sync(0xffffffffu, inc, d);
        if (lane >= d) inc += u;
    }
    if (lane == 31) wsum[wid] = inc;
    __syncthreads();
    if (wid == 0) {
        int wv = wsum[lane];
#pragma unroll
        for (int d = 1; d < 32; d <<= 1) {
            int u = __shfl_up_sync(0xffffffffu, wv, d);
            if (lane >= d) wv += u;
        }
        wsum[lane] = wv;
    }
    __syncthreads();
    int excl = inc - run + (wid ? wsum[wid - 1] : 0);
#pragma unroll
    for (int i = 0; i < 10; i++) {
        int idx = base + i;
        if (idx < NN) {
            int v = excl + loc[i];
            g_off[idx] = v;
            g_cur[idx] = v;
        }
    }
    if (t == 0) g_off[NN] = EE;
}

// ---------------- scatter + zero counters for the NEXT call -----------------
__global__ __launch_bounds__(256) void scatter_kernel(
    const int* __restrict__ ei, const float* __restrict__ ea) {
    __shared__ int sIs64;
    int tid = threadIdx.x;
    int e = blockIdx.x * 256 + tid;
    if (tid == 0) {
        int z = 1;
        for (int i = 1; i < 64; i += 2)
            if (ei[i] != 0) z = 0;
        sIs64 = z;
    }
    __syncthreads();
    int s, d;
    if (sIs64) {
        s = (int)((const long long*)ei)[e];
        d = (int)((const long long*)ei)[(size_t)EE + e];
    } else {
        s = ei[e];
        d = ei[EE + e];
    }
    s = min(max(s, 0), NN - 1);
    d = min(max(d, 0), NN - 1);
    int pos = atomicAdd(&g_cur[d], 1);
    g_cs[pos] = make_int2(s, __float_as_int(ea[e]));
    // scan has consumed g_cnt; zero it here for the next invocation
    if (e < NN) g_cnt[e] = 0;
}

// ---------------- bf16-split tensor-core GEMM + fused att epilogue ----------
// h = x @ W  (M=40000, K=128, N=256). Block tile 64 rows x 128 cols (2 heads),
// warp tile 32x32 (2 m16 x 4 n8, 24 MMAs/warp/kc). A staged once, PRE-PACKED
// as interleaved (bf16x2 hi, lo) uint2 -> fragment = 1 LDS.64, no mainloop
// packing ALU. B single-buffered with register prefetch across the sync.
__device__ __forceinline__ float bhi(float x) {          // bf16-truncated value
    return __uint_as_float(__float_as_uint(x) & 0xffff0000u);
}
__device__ __forceinline__ uint32_t packhi(float a, float b) {   // {a.hi16, b.hi16<<16}
    return __byte_perm(__float_as_uint(a), __float_as_uint(b), 0x7632);
}
__device__ __forceinline__ uint32_t packlo(float a, float b) {   // rn residuals
    uint32_t r;
    asm("cvt.rn.bf16x2.f32 %0, %1, %2;" : "=r"(r)
        : "f"(b - bhi(b)), "f"(a - bhi(a)));             // first src -> high half
    return r;
}

__global__ __launch_bounds__(256) void gemm_kernel(
    const float* __restrict__ A, const float* __restrict__ W,
    const float* __restrict__ att_src, const float* __restrict__ att_dst) {
    __shared__ uint2  Aps[64][68];       // [row][k/2] = (hi bf16x2, lo bf16x2); pitch 68
    __shared__ float4 Bs[128][5];        // [col][tig] = (bh0,bh1,bl0,bl1), pad 5
    __shared__ float2 red[64][2][2];     // [row][head_l][colhalf] = (s,d)

    int t = threadIdx.x;
    int w = t >> 5, lane = t & 31, gid = lane >> 2, tig = lane & 3;
    int rowBase = blockIdx.x * 64;
    int colBase = blockIdx.y * 128;      // within HO
    int wr = (w & 1) * 32, wc = (w >> 1) * 32;

    // ---- stage A tile (64x128 fp32), coalesced, pre-packed hi/lo ----
    {
        const float* Ab = A + (size_t)rowBase * DD;
#pragma unroll
        for (int p = 0; p < 8; p++) {
            int idx = p * 1024 + t * 4;
            float4 v = *(const float4*)(Ab + idx);
            uint4 pk;
            pk.x = packhi(v.x, v.y); pk.y = packlo(v.x, v.y);
            pk.z = packhi(v.z, v.w); pk.w = packlo(v.z, v.w);
            *(uint4*)&Aps[idx >> 7][(idx & 127) >> 1] = pk;
        }
    }

    // ---- B staging setup: thread stages slots s0 and s0+2 of column scol ----
    int scol = t & 127, s0 = t >> 7;
    const float* WpA = W + colBase + scol;
    {
#pragma unroll
        for (int q = 0; q < 2; q++) {
            int s = s0 + q * 2;
            const float* p = WpA + (size_t)(2 * s) * HO;
            float w0 = p[0], w1 = p[HO], w2 = p[8 * HO], w3 = p[9 * HO];
            Bs[scol][s] = make_float4(__uint_as_float(packhi(w0, w1)),
                                      __uint_as_float(packhi(w2, w3)),
                                      __uint_as_float(packlo(w0, w1)),
                                      __uint_as_float(packlo(w2, w3)));
        }
    }
    __syncthreads();

    float acc[2][4][4];
#pragma unroll
    for (int mt = 0; mt < 2; mt++)
#pragma unroll
        for (int nt = 0; nt < 4; nt++)
#pragma unroll
            for (int j = 0; j < 4; j++) acc[mt][nt][j] = 0.f;

#pragma unroll
    for (int kc = 0; kc < 8; kc++) {
        float wreg[2][4];
        if (kc < 7) {                                // prefetch next W chunk
#pragma unroll
            for (int q = 0; q < 2; q++) {
                int s = s0 + q * 2;
                const float* p = WpA + (size_t)((kc + 1) * 16 + 2 * s) * HO;
                wreg[q][0] = p[0];      wreg[q][1] = p[HO];
                wreg[q][2] = p[8 * HO]; wreg[q][3] = p[9 * HO];
            }
        }

#pragma unroll
        for (int mt = 0; mt < 2; mt++) {
            int r0 = wr + mt * 16 + gid, r1 = r0 + 8;
            uint2 a0 = Aps[r0][kc * 8 + tig];         // row0, k-lo  (hi,lo)
            uint2 a1 = Aps[r1][kc * 8 + tig];         // row1, k-lo
            uint2 a2 = Aps[r0][kc * 8 + 4 + tig];     // row0, k-hi
            uint2 a3 = Aps[r1][kc * 8 + 4 + tig];     // row1, k-hi
#pragma unroll
            for (int nt = 0; nt < 4; nt++) {
                float4 bf = Bs[wc + nt * 8 + gid][tig];
                uint32_t bh0 = __float_as_uint(bf.x), bh1 = __float_as_uint(bf.y);
                uint32_t bl0 = __float_as_uint(bf.z), bl1 = __float_as_uint(bf.w);
#define MMA16(A0,A1,A2,A3,B0,B1)                                             \
                asm volatile(                                                 \
                    "mma.sync.aligned.m16n8k16.row.col.f32.bf16.bf16.f32 "    \
                    "{%0,%1,%2,%3}, {%4,%5,%6,%7}, {%8,%9}, {%0,%1,%2,%3};"   \
                    : "+f"(acc[mt][nt][0]), "+f"(acc[mt][nt][1]),             \
                      "+f"(acc[mt][nt][2]), "+f"(acc[mt][nt][3])              \
                    : "r"(A0), "r"(A1), "r"(A2), "r"(A3), "r"(B0), "r"(B1))
                MMA16(a0.x, a1.x, a2.x, a3.x, bh0, bh1);   // hi*hi
                MMA16(a0.x, a1.x, a2.x, a3.x, bl0, bl1);   // hi*lo
                MMA16(a0.y, a1.y, a2.y, a3.y, bh0, bh1);   // lo*hi
#undef MMA16
            }
        }
        __syncthreads();                             // all warps done reading Bs
        if (kc < 7) {
#pragma unroll
            for (int q = 0; q < 2; q++) {
                int s = s0 + q * 2;
                Bs[scol][s] = make_float4(
                    __uint_as_float(packhi(wreg[q][0], wreg[q][1])),
                    __uint_as_float(packhi(wreg[q][2], wreg[q][3])),
                    __uint_as_float(packlo(wreg[q][0], wreg[q][1])),
                    __uint_as_float(packlo(wreg[q][2], wreg[q][3])));
            }
            __syncthreads();                         // Bs ready for kc+1
        }
    }

    // ---- store h (fp16) + fused att partial dots ----
    int head_l = wc >> 6;                            // 0 or 1
    int habase = (blockIdx.y * 2 + head_l) * OO;
#pragma unroll
    for (int mt = 0; mt < 2; mt++) {
        int r0 = wr + mt * 16 + gid, r1 = r0 + 8;
        float sa0 = 0.f, da0 = 0.f, sa1 = 0.f, da1 = 0.f;
#pragma unroll
        for (int nt = 0; nt < 4; nt++) {
            int cl = wc + nt * 8 + tig * 2;          // 0..127 within block tile
            int gcol = colBase + cl;
            *(__half2*)&g_hh[(size_t)(rowBase + r0) * HO + gcol] =
                __floats2half2_rn(acc[mt][nt][0], acc[mt][nt][1]);
            *(__half2*)&g_hh[(size_t)(rowBase + r1) * HO + gcol] =
                __floats2half2_rn(acc[mt][nt][2], acc[mt][nt][3]);
            int ch = cl & 63;                        // col within head
            float as0 = att_src[habase + ch], as1 = att_src[habase + ch + 1];
            float ad0 = att_dst[habase + ch], ad1 = att_dst[habase + ch + 1];
            sa0 += acc[mt][nt][0] * as0 + acc[mt][nt][1] * as1;
            da0 += acc[mt][nt][0] * ad0 + acc[mt][nt][1] * ad1;
            sa1 += acc[mt][nt][2] * as0 + acc[mt][nt][3] * as1;
            da1 += acc[mt][nt][2] * ad0 + acc[mt][nt][3] * ad1;
        }
#pragma unroll
        for (int d = 1; d < 4; d <<= 1) {            // reduce over tig
            sa0 += __shfl_xor_sync(0xffffffffu, sa0, d);
            da0 += __shfl_xor_sync(0xffffffffu, da0, d);
            sa1 += __shfl_xor_sync(0xffffffffu, sa1, d);
            da1 += __shfl_xor_sync(0xffffffffu, da1, d);
        }
        if (tig == 0) {
            int chh = (wc >> 5) & 1;                 // which 32-col half of the head
            red[r0][head_l][chh] = make_float2(sa0, da0);
            red[r1][head_l][chh] = make_float2(sa1, da1);
        }
    }
    __syncthreads();
    if (t < 128) {
        int row = t & 63, hl = t >> 6;
        float2 a = red[row][hl][0], b = red[row][hl][1];
        int grow = rowBase + row;
        int head = blockIdx.y * 2 + hl;
        g_asrc[grow * 4 + head] = a.x + b.x;
        g_adst[grow * 4 + head] = a.y + b.y;
    }
}

// ---------------- fused segment-softmax + aggregation (no-max exp) ----------
__device__ __forceinline__ float lrelu(float a) {
    return fmaxf(a, 0.f) + 0.2f * fminf(a, 0.f);
}

__global__ __launch_bounds__(256) void agg_kernel(float* __restrict__ out,
                                                  const float* __restrict__ bias) {
    __shared__ float4 s_w[8][32];
    __shared__ int    s_idx[8][32];

    int gw = (blockIdx.x * blockDim.x + threadIdx.x) >> 5;   // 0..MM-1 exact
    int w = threadIdx.x >> 5;
    int lane = threadIdx.x & 31;
    int n = gw >> 2;
    int b = gw & 3;
    int beg = g_off[n], end = g_off[n + 1];

    float4 ad = *(const float4*)&g_adst[(b * NN + n) * 4];
    float4 ce = g_cedge;
    int myhead = lane >> 3;
    const __half* hbase = g_hh + (size_t)(b * NN) * HO + lane * 8;

    float S0 = 0.f, S1 = 0.f, S2 = 0.f, S3 = 0.f;   // per-lane partials
    float acc[8] = {0, 0, 0, 0, 0, 0, 0, 0};

    for (int c0 = beg; c0 < end; c0 += 32) {
        int i = c0 + lane;
        float p0 = 0.f, p1 = 0.f, p2 = 0.f, p3 = 0.f;
        int sidx = 0;
        if (i < end) {
            int2 e = g_cs[i];
            sidx = e.x;
            float ww = __int_as_float(e.y);
            float4 as = *(const float4*)&g_asrc[(b * NN + sidx) * 4];
            p0 = __expf(lrelu(as.x + ad.x + ww * ce.x));
            p1 = __expf(lrelu(as.y + ad.y + ww * ce.y));
            p2 = __expf(lrelu(as.z + ad.z + ww * ce.z));
            p3 = __expf(lrelu(as.w + ad.w + ww * ce.w));
            S0 += p0; S1 += p1; S2 += p2; S3 += p3;
        }
        s_idx[w][lane] = sidx;
        s_w[w][lane] = make_float4(p0, p1, p2, p3);
        __syncwarp();

        int cnt = min(32, end - c0);
#pragma unroll 8
        for (int j = 0; j < cnt; j++) {
            int sj = s_idx[w][j];
            float wj = ((const float*)&s_w[w][j])[myhead];
            int4 pk = *(const int4*)(hbase + (size_t)sj * HO);
            float2 f0 = __half22float2(*(__half2*)&pk.x);
            float2 f1 = __half22float2(*(__half2*)&pk.y);
            float2 f2 = __half22float2(*(__half2*)&pk.z);
            float2 f3 = __half22float2(*(__half2*)&pk.w);
            acc[0] = fmaf(wj, f0.x, acc[0]); acc[1] = fmaf(wj, f0.y, acc[1]);
            acc[2] = fmaf(wj, f1.x, acc[2]); acc[3] = fmaf(wj, f1.y, acc[3]);
            acc[4] = fmaf(wj, f2.x, acc[4]); acc[5] = fmaf(wj, f2.y, acc[5]);
            acc[6] = fmaf(wj, f3.x, acc[6]); acc[7] = fmaf(wj, f3.y, acc[7]);
        }
        __syncwarp();
    }

    // one warp-reduction of S per head, at the end only
#pragma unroll
    for (int d = 16; d; d >>= 1) {
        S0 += __shfl_xor_sync(0xffffffffu, S0, d);
        S1 += __shfl_xor_sync(0xffffffffu, S1, d);
        S2 += __shfl_xor_sync(0xffffffffu, S2, d);
        S3 += __shfl_xor_sync(0xffffffffu, S3, d);
    }
    float Sh = (myhead == 0) ? S0 : (myhead == 1) ? S1 : (myhead == 2) ? S2 : S3;
    float r = 1.f / fmaxf(Sh, 1e-16f);
#pragma unroll
    for (int k = 0; k < 8; k++) acc[k] *= r;

    // mean over heads: lanes l, l^8, l^16, l^24 hold same o, different h
#pragma unroll
    for (int k = 0; k < 8; k++) {
        float v = acc[k];
        v += __shfl_xor_sync(0xffffffffu, v, 8);
        v += __shfl_xor_sync(0xffffffffu, v, 16);
        acc[k] = v;
    }
    if (lane < 8) {
        float* op = out + ((size_t)b * NN + n) * OO + lane * 8;
#pragma unroll
        for (int k = 0; k < 8; k++)
            op[k] = acc[k] * 0.25f + bias[lane * 8 + k];
    }
}

// ---------------- launch ----------------------------------------------------
extern "C" void kernel_launch(void* const* d_in, const int* in_sizes, int n_in,
                              void* d_out, int out_size) {
    const float* x        = (const float*)d_in[0];
    const void*  ei       = d_in[1];
    const float* ea       = (const float*)d_in[2];
    const float* Wsrc     = (const float*)d_in[3];
    const float* att_src  = (const float*)d_in[4];
    const float* att_dst  = (const float*)d_in[5];
    const float* Wedge    = (const float*)d_in[6];
    const float* att_edge = (const float*)d_in[7];
    const float* bias     = (const float*)d_in[8];
    float* out = (float*)d_out;

    static cudaStream_t s_csr = nullptr;
    static cudaEvent_t  ev_fork = nullptr, ev_join = nullptr;
    if (s_csr == nullptr) {
        cudaStreamCreateWithFlags(&s_csr, cudaStreamNonBlocking);
        cudaEventCreateWithFlags(&ev_fork, cudaEventDisableTiming);
        cudaEventCreateWithFlags(&ev_join, cudaEventDisableTiming);
    }

    // fork: CSR chain on side stream, GEMM on main stream, join before agg
    cudaEventRecord(ev_fork, 0);
    cudaStreamWaitEvent(s_csr, ev_fork, 0);

    hist_kernel<<<EE / 256, 256, 0, s_csr>>>((const int*)ei, Wedge, att_edge);
    scan_kernel<<<1, 1024, 0, s_csr>>>();
    scatter_kernel<<<EE / 256, 256, 0, s_csr>>>((const int*)ei, ea);
    cudaEventRecord(ev_join, s_csr);

    gemm_kernel<<<dim3(MM / 64, HO / 128), 256>>>(x, Wsrc, att_src, att_dst);

    cudaStreamWaitEvent(0, ev_join, 0);
    agg_kernel<<<MM / 8, 256>>>(out, bias);
}

// round 15
// speedup vs baseline: 1.2762x; 1.0127x over previous
#include <cuda_runtime.h>
#include <cuda_fp16.h>
#include <cuda_bf16.h>
#include <cstdint>

#define NN 10000
#define BB 4
#define EE 160000
#define DD 128
#define HH 4
#define OO 64
#define HO 256            // H*O
#define MM (BB*NN)        // 40000 rows

// dynamic smem layout for gemm_kernel
#define APS_BYTES (64 * 68 * 8)            // uint2 Aps[64][68]   = 34816
#define BS_BYTES  (2 * 128 * 5 * 16)       // float4 Bs[2][128][5] = 20480
#define RED_BYTES (64 * 2 * 2 * 8)         // float2 red[64][2][2] = 2048
#define GEMM_SMEM (APS_BYTES + BS_BYTES + RED_BYTES)   // 57344

// ---------------- scratch (device globals; no allocation allowed) ----------
__device__ __half g_hh[(size_t)MM * HO];   // projected features, fp16 [b*N+n][h*64+o]
__device__ float g_asrc[MM * HH];          // [b*N+n][h]
__device__ float g_adst[MM * HH];
__device__ float4 g_cedge;                 // c[h] = sum_o W_edge[h,o]*att_edge[h,o]
__device__ int   g_cnt[NN];                // zero-init; re-zeroed by scatter tail
__device__ int   g_off[NN + 1];
__device__ int   g_cur[NN];
__device__ int2  g_cs[EE];                 // packed (src, __float_as_int(ea)) per CSR slot

// ---------------- hist: per-block dtype detect + histogram + cedge ----------
__global__ __launch_bounds__(256) void hist_kernel(
    const int* __restrict__ ei, const float* __restrict__ W_edge,
    const float* __restrict__ att_edge) {
    __shared__ int sIs64;
    int tid = threadIdx.x;
    int e = blockIdx.x * 256 + tid;          // 0..EE-1 exactly
    if (tid == 0) {
        int z = 1;
        for (int i = 1; i < 64; i += 2)
            if (ei[i] != 0) z = 0;
        sIs64 = z;
    }
    __syncthreads();
    int d;
    if (sIs64) d = (int)((const long long*)ei)[(size_t)EE + e];
    else       d = ei[EE + e];
    d = min(max(d, 0), NN - 1);
    atomicAdd(&g_cnt[d], 1);

    if (blockIdx.x == 0 && tid < 128) {      // cedge (independent)
        int head = tid >> 5, lane = tid & 31;
        float cs = W_edge[head * OO + lane] * att_edge[head * OO + lane]
                 + W_edge[head * OO + lane + 32] * att_edge[head * OO + lane + 32];
#pragma unroll
        for (int dd = 16; dd; dd >>= 1) cs += __shfl_xor_sync(0xffffffffu, cs, dd);
        if (lane == 0) ((float*)&g_cedge)[head] = cs;
    }
}

// ---------------- exclusive scan of counts (single block) -------------------
__global__ void scan_kernel() {
    __shared__ int wsum[32];
    int t = threadIdx.x;
    int base = t * 10;
    int loc[10];
    int run = 0;
#pragma unroll
    for (int i = 0; i < 10; i++) {
        int idx = base + i;
        int c = (idx < NN) ? g_cnt[idx] : 0;
        loc[i] = run;
        run += c;
    }
    int lane = t & 31, wid = t >> 5;
    int inc = run;
#pragma unroll
    for (int d = 1; d < 32; d <<= 1) {
        int u = __shfl_up_sync(0xffffffffu, inc, d);
        if (lane >= d) inc += u;
    }
    if (lane == 31) wsum[wid] = inc;
    __syncthreads();
    if (wid == 0) {
        int wv = wsum[lane];
#pragma unroll
        for (int d = 1; d < 32; d <<= 1) {
            int u = __shfl_up_sync(0xffffffffu, wv, d);
            if (lane >= d) wv += u;
        }
        wsum[lane] = wv;
    }
    __syncthreads();
    int excl = inc - run + (wid ? wsum[wid - 1] : 0);
#pragma unroll
    for (int i = 0; i < 10; i++) {
        int idx = base + i;
        if (idx < NN) {
            int v = excl + loc[i];
            g_off[idx] = v;
            g_cur[idx] = v;
        }
    }
    if (t == 0) g_off[NN] = EE;
}

// ---------------- scatter + zero counters for the NEXT call -----------------
__global__ __launch_bounds__(256) void scatter_kernel(
    const int* __restrict__ ei, const float* __restrict__ ea) {
    __shared__ int sIs64;
    int tid = threadIdx.x;
    int e = blockIdx.x * 256 + tid;
    if (tid == 0) {
        int z = 1;
        for (int i = 1; i < 64; i += 2)
            if (ei[i] != 0) z = 0;
        sIs64 = z;
    }
    __syncthreads();
    int s, d;
    if (sIs64) {
        s = (int)((const long long*)ei)[e];
        d = (int)((const long long*)ei)[(size_t)EE + e];
    } else {
        s = ei[e];
        d = ei[EE + e];
    }
    s = min(max(s, 0), NN - 1);
    d = min(max(d, 0), NN - 1);
    int pos = atomicAdd(&g_cur[d], 1);
    g_cs[pos] = make_int2(s, __float_as_int(ea[e]));
    // scan has consumed g_cnt; zero it here for the next invocation
    if (e < NN) g_cnt[e] = 0;
}

// ---------------- bf16-split tensor-core GEMM + fused att epilogue ----------
// h = x @ W  (M=40000, K=128, N=256). Block tile 64 rows x 128 cols (2 heads),
// warp tile 32x32. A staged once pre-packed (hi,lo). B DOUBLE-buffered in
// dynamic smem: W(kc+1) goes gmem->pack->STS into buf^1 while MMAs(kc) run;
// exactly ONE __syncthreads per kc. launch_bounds(256,3) for occupancy.
__device__ __forceinline__ float bhi(float x) {          // bf16-truncated value
    return __uint_as_float(__float_as_uint(x) & 0xffff0000u);
}
__device__ __forceinline__ uint32_t packhi(float a, float b) {   // {a.hi16, b.hi16<<16}
    return __byte_perm(__float_as_uint(a), __float_as_uint(b), 0x7632);
}
__device__ __forceinline__ uint32_t packlo(float a, float b) {   // rn residuals
    uint32_t r;
    asm("cvt.rn.bf16x2.f32 %0, %1, %2;" : "=r"(r)
        : "f"(b - bhi(b)), "f"(a - bhi(a)));             // first src -> high half
    return r;
}

__global__ __launch_bounds__(256, 3) void gemm_kernel(
    const float* __restrict__ A, const float* __restrict__ W,
    const float* __restrict__ att_src, const float* __restrict__ att_dst) {
    extern __shared__ unsigned char dynsmem[];
    uint2  (*Aps)[68]     = (uint2(*)[68])dynsmem;                    // [64][68]
    float4 (*Bs)[128][5]  = (float4(*)[128][5])(dynsmem + APS_BYTES); // [2][128][5]
    float2 (*red)[2][2]   = (float2(*)[2][2])(dynsmem + APS_BYTES + BS_BYTES);

    int t = threadIdx.x;
    int w = t >> 5, lane = t & 31, gid = lane >> 2, tig = lane & 3;
    int rowBase = blockIdx.x * 64;
    int colBase = blockIdx.y * 128;      // within HO
    int wr = (w & 1) * 32, wc = (w >> 1) * 32;

    // ---- stage A tile (64x128 fp32), coalesced, pre-packed hi/lo ----
    {
        const float* Ab = A + (size_t)rowBase * DD;
#pragma unroll
        for (int p = 0; p < 8; p++) {
            int idx = p * 1024 + t * 4;
            float4 v = *(const float4*)(Ab + idx);
            uint4 pk;
            pk.x = packhi(v.x, v.y); pk.y = packlo(v.x, v.y);
            pk.z = packhi(v.z, v.w); pk.w = packlo(v.z, v.w);
            *(uint4*)&Aps[idx >> 7][(idx & 127) >> 1] = pk;
        }
    }

    // ---- B staging: thread stages slots s0, s0+2 of column scol ----
    int scol = t & 127, s0 = t >> 7;
    const float* WpA = W + colBase + scol;
    {
#pragma unroll
        for (int q = 0; q < 2; q++) {
            int s = s0 + q * 2;
            const float* p = WpA + (size_t)(2 * s) * HO;
            float w0 = p[0], w1 = p[HO], w2 = p[8 * HO], w3 = p[9 * HO];
            Bs[0][scol][s] = make_float4(__uint_as_float(packhi(w0, w1)),
                                         __uint_as_float(packhi(w2, w3)),
                                         __uint_as_float(packlo(w0, w1)),
                                         __uint_as_float(packlo(w2, w3)));
        }
    }
    __syncthreads();

    float acc[2][4][4];
#pragma unroll
    for (int mt = 0; mt < 2; mt++)
#pragma unroll
        for (int nt = 0; nt < 4; nt++)
#pragma unroll
            for (int j = 0; j < 4; j++) acc[mt][nt][j] = 0.f;

#pragma unroll
    for (int kc = 0; kc < 8; kc++) {
        int buf = kc & 1;
        if (kc < 7) {                    // prefetch W(kc+1) straight into buf^1
#pragma unroll
            for (int q = 0; q < 2; q++) {
                int s = s0 + q * 2;
                const float* p = WpA + (size_t)((kc + 1) * 16 + 2 * s) * HO;
                float w0 = p[0], w1 = p[HO], w2 = p[8 * HO], w3 = p[9 * HO];
                Bs[buf ^ 1][scol][s] = make_float4(
                    __uint_as_float(packhi(w0, w1)),
                    __uint_as_float(packhi(w2, w3)),
                    __uint_as_float(packlo(w0, w1)),
                    __uint_as_float(packlo(w2, w3)));
            }
        }

#pragma unroll
        for (int mt = 0; mt < 2; mt++) {
            int r0 = wr + mt * 16 + gid, r1 = r0 + 8;
            uint2 a0 = Aps[r0][kc * 8 + tig];         // row0, k-lo  (hi,lo)
            uint2 a1 = Aps[r1][kc * 8 + tig];         // row1, k-lo
            uint2 a2 = Aps[r0][kc * 8 + 4 + tig];     // row0, k-hi
            uint2 a3 = Aps[r1][kc * 8 + 4 + tig];     // row1, k-hi
#pragma unroll
            for (int nt = 0; nt < 4; nt++) {
                float4 bf = Bs[buf][wc + nt * 8 + gid][tig];
                uint32_t bh0 = __float_as_uint(bf.x), bh1 = __float_as_uint(bf.y);
                uint32_t bl0 = __float_as_uint(bf.z), bl1 = __float_as_uint(bf.w);
#define MMA16(A0,A1,A2,A3,B0,B1)                                             \
                asm volatile(                                                 \
                    "mma.sync.aligned.m16n8k16.row.col.f32.bf16.bf16.f32 "    \
                    "{%0,%1,%2,%3}, {%4,%5,%6,%7}, {%8,%9}, {%0,%1,%2,%3};"   \
                    : "+f"(acc[mt][nt][0]), "+f"(acc[mt][nt][1]),             \
                      "+f"(acc[mt][nt][2]), "+f"(acc[mt][nt][3])              \
                    : "r"(A0), "r"(A1), "r"(A2), "r"(A3), "r"(B0), "r"(B1))
                MMA16(a0.x, a1.x, a2.x, a3.x, bh0, bh1);   // hi*hi
                MMA16(a0.x, a1.x, a2.x, a3.x, bl0, bl1);   // hi*lo
                MMA16(a0.y, a1.y, a2.y, a3.y, bh0, bh1);   // lo*hi
#undef MMA16
            }
        }
        __syncthreads();   // buf^1 staged AND buf consumed -> safe to swap
    }

    // ---- store h (fp16) + fused att partial dots ----
    int head_l = wc >> 6;                            // 0 or 1
    int habase = (blockIdx.y * 2 + head_l) * OO;
#pragma unroll
    for (int mt = 0; mt < 2; mt++) {
        int r0 = wr + mt * 16 + gid, r1 = r0 + 8;
        float sa0 = 0.f, da0 = 0.f, sa1 = 0.f, da1 = 0.f;
#pragma unroll
        for (int nt = 0; nt < 4; nt++) {
            int cl = wc + nt * 8 + tig * 2;          // 0..127 within block tile
            int gcol = colBase + cl;
            *(__half2*)&g_hh[(size_t)(rowBase + r0) * HO + gcol] =
                __floats2half2_rn(acc[mt][nt][0], acc[mt][nt][1]);
            *(__half2*)&g_hh[(size_t)(rowBase + r1) * HO + gcol] =
                __floats2half2_rn(acc[mt][nt][2], acc[mt][nt][3]);
            int ch = cl & 63;                        // col within head
            float as0 = att_src[habase + ch], as1 = att_src[habase + ch + 1];
            float ad0 = att_dst[habase + ch], ad1 = att_dst[habase + ch + 1];
            sa0 += acc[mt][nt][0] * as0 + acc[mt][nt][1] * as1;
            da0 += acc[mt][nt][0] * ad0 + acc[mt][nt][1] * ad1;
            sa1 += acc[mt][nt][2] * as0 + acc[mt][nt][3] * as1;
            da1 += acc[mt][nt][2] * ad0 + acc[mt][nt][3] * ad1;
        }
#pragma unroll
        for (int d = 1; d < 4; d <<= 1) {            // reduce over tig
            sa0 += __shfl_xor_sync(0xffffffffu, sa0, d);
            da0 += __shfl_xor_sync(0xffffffffu, da0, d);
            sa1 += __shfl_xor_sync(0xffffffffu, sa1, d);
            da1 += __shfl_xor_sync(0xffffffffu, da1, d);
        }
        if (tig == 0) {
            int chh = (wc >> 5) & 1;                 // which 32-col half of the head
            red[r0][head_l][chh] = make_float2(sa0, da0);
            red[r1][head_l][chh] = make_float2(sa1, da1);
        }
    }
    __syncthreads();
    if (t < 128) {
        int row = t & 63, hl = t >> 6;
        float2 a = red[row][hl][0], b = red[row][hl][1];
        int grow = rowBase + row;
        int head = blockIdx.y * 2 + hl;
        g_asrc[grow * 4 + head] = a.x + b.x;
        g_adst[grow * 4 + head] = a.y + b.y;
    }
}

// ---------------- fused segment-softmax + aggregation (no-max exp) ----------
__device__ __forceinline__ float lrelu(float a) {
    return fmaxf(a, 0.f) + 0.2f * fminf(a, 0.f);
}

__global__ __launch_bounds__(256) void agg_kernel(float* __restrict__ out,
                                                  const float* __restrict__ bias) {
    __shared__ float4 s_w[8][32];
    __shared__ int    s_idx[8][32];

    int gw = (blockIdx.x * blockDim.x + threadIdx.x) >> 5;   // 0..MM-1 exact
    int w = threadIdx.x >> 5;
    int lane = threadIdx.x & 31;
    int n = gw >> 2;
    int b = gw & 3;
    int beg = g_off[n], end = g_off[n + 1];

    float4 ad = *(const float4*)&g_adst[(b * NN + n) * 4];
    float4 ce = g_cedge;
    int myhead = lane >> 3;
    const __half* hbase = g_hh + (size_t)(b * NN) * HO + lane * 8;

    float S0 = 0.f, S1 = 0.f, S2 = 0.f, S3 = 0.f;   // per-lane partials
    float acc[8] = {0, 0, 0, 0, 0, 0, 0, 0};

    for (int c0 = beg; c0 < end; c0 += 32) {
        int i = c0 + lane;
        float p0 = 0.f, p1 = 0.f, p2 = 0.f, p3 = 0.f;
        int sidx = 0;
        if (i < end) {
            int2 e = g_cs[i];
            sidx = e.x;
            float ww = __int_as_float(e.y);
            float4 as = *(const float4*)&g_asrc[(b * NN + sidx) * 4];
            p0 = __expf(lrelu(as.x + ad.x + ww * ce.x));
            p1 = __expf(lrelu(as.y + ad.y + ww * ce.y));
            p2 = __expf(lrelu(as.z + ad.z + ww * ce.z));
            p3 = __expf(lrelu(as.w + ad.w + ww * ce.w));
            S0 += p0; S1 += p1; S2 += p2; S3 += p3;
        }
        s_idx[w][lane] = sidx;
        s_w[w][lane] = make_float4(p0, p1, p2, p3);
        __syncwarp();

        int cnt = min(32, end - c0);
#pragma unroll 8
        for (int j = 0; j < cnt; j++) {
            int sj = s_idx[w][j];
            float wj = ((const float*)&s_w[w][j])[myhead];
            int4 pk = *(const int4*)(hbase + (size_t)sj * HO);
            float2 f0 = __half22float2(*(__half2*)&pk.x);
            float2 f1 = __half22float2(*(__half2*)&pk.y);
            float2 f2 = __half22float2(*(__half2*)&pk.z);
            float2 f3 = __half22float2(*(__half2*)&pk.w);
            acc[0] = fmaf(wj, f0.x, acc[0]); acc[1] = fmaf(wj, f0.y, acc[1]);
            acc[2] = fmaf(wj, f1.x, acc[2]); acc[3] = fmaf(wj, f1.y, acc[3]);
            acc[4] = fmaf(wj, f2.x, acc[4]); acc[5] = fmaf(wj, f2.y, acc[5]);
            acc[6] = fmaf(wj, f3.x, acc[6]); acc[7] = fmaf(wj, f3.y, acc[7]);
        }
        __syncwarp();
    }

    // one warp-reduction of S per head, at the end only
#pragma unroll
    for (int d = 16; d; d >>= 1) {
        S0 += __shfl_xor_sync(0xffffffffu, S0, d);
        S1 += __shfl_xor_sync(0xffffffffu, S1, d);
        S2 += __shfl_xor_sync(0xffffffffu, S2, d);
        S3 += __shfl_xor_sync(0xffffffffu, S3, d);
    }
    float Sh = (myhead == 0) ? S0 : (myhead == 1) ? S1 : (myhead == 2) ? S2 : S3;
    float r = 1.f / fmaxf(Sh, 1e-16f);
#pragma unroll
    for (int k = 0; k < 8; k++) acc[k] *= r;

    // mean over heads: lanes l, l^8, l^16, l^24 hold same o, different h
#pragma unroll
    for (int k = 0; k < 8; k++) {
        float v = acc[k];
        v += __shfl_xor_sync(0xffffffffu, v, 8);
        v += __shfl_xor_sync(0xffffffffu, v, 16);
        acc[k] = v;
    }
    if (lane < 8) {
        float* op = out + ((size_t)b * NN + n) * OO + lane * 8;
#pragma unroll
        for (int k = 0; k < 8; k++)
            op[k] = acc[k] * 0.25f + bias[lane * 8 + k];
    }
}

// ---------------- launch ----------------------------------------------------
extern "C" void kernel_launch(void* const* d_in, const int* in_sizes, int n_in,
                              void* d_out, int out_size) {
    const float* x        = (const float*)d_in[0];
    const void*  ei       = d_in[1];
    const float* ea       = (const float*)d_in[2];
    const float* Wsrc     = (const float*)d_in[3];
    const float* att_src  = (const float*)d_in[4];
    const float* att_dst  = (const float*)d_in[5];
    const float* Wedge    = (const float*)d_in[6];
    const float* att_edge = (const float*)d_in[7];
    const float* bias     = (const float*)d_in[8];
    float* out = (float*)d_out;

    static cudaStream_t s_csr = nullptr;
    static cudaEvent_t  ev_fork = nullptr, ev_join = nullptr;
    if (s_csr == nullptr) {
        cudaStreamCreateWithFlags(&s_csr, cudaStreamNonBlocking);
        cudaEventCreateWithFlags(&ev_fork, cudaEventDisableTiming);
        cudaEventCreateWithFlags(&ev_join, cudaEventDisableTiming);
        cudaFuncSetAttribute(gemm_kernel,
                             cudaFuncAttributeMaxDynamicSharedMemorySize,
                             GEMM_SMEM);
    }

    // fork: CSR chain on side stream, GEMM on main stream, join before agg
    cudaEventRecord(ev_fork, 0);
    cudaStreamWaitEvent(s_csr, ev_fork, 0);

    hist_kernel<<<EE / 256, 256, 0, s_csr>>>((const int*)ei, Wedge, att_edge);
    scan_kernel<<<1, 1024, 0, s_csr>>>();
    scatter_kernel<<<EE / 256, 256, 0, s_csr>>>((const int*)ei, ea);
    cudaEventRecord(ev_join, s_csr);

    gemm_kernel<<<dim3(MM / 64, HO / 128), 256, GEMM_SMEM>>>(x, Wsrc, att_src, att_dst);

    cudaStreamWaitEvent(0, ev_join, 0);
    agg_kernel<<<MM / 8, 256>>>(out, bias);
}

// round 16
// speedup vs baseline: 1.2854x; 1.0072x over previous
#include <cuda_runtime.h>
#include <cuda_fp16.h>
#include <cuda_bf16.h>
#include <cstdint>

#define NN 10000
#define BB 4
#define EE 160000
#define DD 128
#define HH 4
#define OO 64
#define HO 256            // H*O
#define MM (BB*NN)        // 40000 rows

// dynamic smem layout for gemm_kernel
#define APS_BYTES (64 * 68 * 8)            // uint2 Aps[64][68]    = 34816
#define BS_BYTES  (8 * 128 * 4 * 16)       // float4 Bs[8][128][4] = 65536
#define RED_BYTES (64 * 2 * 2 * 8)         // float2 red[64][2][2] = 2048
#define GEMM_SMEM (APS_BYTES + BS_BYTES + RED_BYTES)   // 102400

// ---------------- scratch (device globals; no allocation allowed) ----------
__device__ __half g_hh[(size_t)MM * HO];   // projected features, fp16 [b*N+n][h*64+o]
__device__ float g_asrc[MM * HH];          // [b*N+n][h]
__device__ float g_adst[MM * HH];
__device__ float4 g_cedge;                 // c[h] = sum_o W_edge[h,o]*att_edge[h,o]
__device__ int   g_cnt[NN];                // zero-init; re-zeroed by scatter tail
__device__ int   g_off[NN + 1];
__device__ int   g_cur[NN];
__device__ int2  g_cs[EE];                 // packed (src, __float_as_int(ea)) per CSR slot

// ---------------- hist: per-block dtype detect + histogram + cedge ----------
__global__ __launch_bounds__(256) void hist_kernel(
    const int* __restrict__ ei, const float* __restrict__ W_edge,
    const float* __restrict__ att_edge) {
    __shared__ int sIs64;
    int tid = threadIdx.x;
    int e = blockIdx.x * 256 + tid;          // 0..EE-1 exactly
    if (tid == 0) {
        int z = 1;
        for (int i = 1; i < 64; i += 2)
            if (ei[i] != 0) z = 0;
        sIs64 = z;
    }
    __syncthreads();
    int d;
    if (sIs64) d = (int)((const long long*)ei)[(size_t)EE + e];
    else       d = ei[EE + e];
    d = min(max(d, 0), NN - 1);
    atomicAdd(&g_cnt[d], 1);

    if (blockIdx.x == 0 && tid < 128) {      // cedge (independent)
        int head = tid >> 5, lane = tid & 31;
        float cs = W_edge[head * OO + lane] * att_edge[head * OO + lane]
                 + W_edge[head * OO + lane + 32] * att_edge[head * OO + lane + 32];
#pragma unroll
        for (int dd = 16; dd; dd >>= 1) cs += __shfl_xor_sync(0xffffffffu, cs, dd);
        if (lane == 0) ((float*)&g_cedge)[head] = cs;
    }
}

// ---------------- exclusive scan of counts (single block) -------------------
__global__ void scan_kernel() {
    __shared__ int wsum[32];
    int t = threadIdx.x;
    int base = t * 10;
    int loc[10];
    int run = 0;
#pragma unroll
    for (int i = 0; i < 10; i++) {
        int idx = base + i;
        int c = (idx < NN) ? g_cnt[idx] : 0;
        loc[i] = run;
        run += c;
    }
    int lane = t & 31, wid = t >> 5;
    int inc = run;
#pragma unroll
    for (int d = 1; d < 32; d <<= 1) {
        int u = __shfl_up_sync(0xffffffffu, inc, d);
        if (lane >= d) inc += u;
    }
    if (lane == 31) wsum[wid] = inc;
    __syncthreads();
    if (wid == 0) {
        int wv = wsum[lane];
#pragma unroll
        for (int d = 1; d < 32; d <<= 1) {
            int u = __shfl_up_sync(0xffffffffu, wv, d);
            if (lane >= d) wv += u;
        }
        wsum[lane] = wv;
    }
    __syncthreads();
    int excl = inc - run + (wid ? wsum[wid - 1] : 0);
#pragma unroll
    for (int i = 0; i < 10; i++) {
        int idx = base + i;
        if (idx < NN) {
            int v = excl + loc[i];
            g_off[idx] = v;
            g_cur[idx] = v;
        }
    }
    if (t == 0) g_off[NN] = EE;
}

// ---------------- scatter + zero counters for the NEXT call -----------------
__global__ __launch_bounds__(256) void scatter_kernel(
    const int* __restrict__ ei, const float* __restrict__ ea) {
    __shared__ int sIs64;
    int tid = threadIdx.x;
    int e = blockIdx.x * 256 + tid;
    if (tid == 0) {
        int z = 1;
        for (int i = 1; i < 64; i += 2)
            if (ei[i] != 0) z = 0;
        sIs64 = z;
    }
    __syncthreads();
    int s, d;
    if (sIs64) {
        s = (int)((const long long*)ei)[e];
        d = (int)((const long long*)ei)[(size_t)EE + e];
    } else {
        s = ei[e];
        d = ei[EE + e];
    }
    s = min(max(s, 0), NN - 1);
    d = min(max(d, 0), NN - 1);
    int pos = atomicAdd(&g_cur[d], 1);
    g_cs[pos] = make_int2(s, __float_as_int(ea[e]));
    // scan has consumed g_cnt; zero it here for the next invocation
    if (e < NN) g_cnt[e] = 0;
}

// ---------------- bf16-split tensor-core GEMM + fused att epilogue ----------
// h = x @ W  (M=40000, K=128, N=256). Block tile 64 rows x 128 cols (2 heads),
// warp tile 32x32. A pre-packed (hi,lo). FULL B tile (all 8 k-chunks) staged
// once -> ZERO barriers in the mainloop; B fragments hoisted out of mt loop.
__device__ __forceinline__ float bhi(float x) {          // bf16-truncated value
    return __uint_as_float(__float_as_uint(x) & 0xffff0000u);
}
__device__ __forceinline__ uint32_t packhi(float a, float b) {   // {a.hi16, b.hi16<<16}
    return __byte_perm(__float_as_uint(a), __float_as_uint(b), 0x7632);
}
__device__ __forceinline__ uint32_t packlo(float a, float b) {   // rn residuals
    uint32_t r;
    asm("cvt.rn.bf16x2.f32 %0, %1, %2;" : "=r"(r)
        : "f"(b - bhi(b)), "f"(a - bhi(a)));             // first src -> high half
    return r;
}

__global__ __launch_bounds__(256, 2) void gemm_kernel(
    const float* __restrict__ A, const float* __restrict__ W,
    const float* __restrict__ att_src, const float* __restrict__ att_dst) {
    extern __shared__ unsigned char dynsmem[];
    uint2  (*Aps)[68]     = (uint2(*)[68])dynsmem;                     // [64][68]
    float4 (*Bs)[128][4]  = (float4(*)[128][4])(dynsmem + APS_BYTES);  // [8][128][4]
    float2 (*red)[2][2]   = (float2(*)[2][2])(dynsmem + APS_BYTES + BS_BYTES);

    int t = threadIdx.x;
    int w = t >> 5, lane = t & 31, gid = lane >> 2, tig = lane & 3;
    int rowBase = blockIdx.x * 64;
    int colBase = blockIdx.y * 128;      // within HO
    int wr = (w & 1) * 32, wc = (w >> 1) * 32;

    // ---- stage A tile (64x128 fp32), coalesced, pre-packed hi/lo ----
    {
        const float* Ab = A + (size_t)rowBase * DD;
#pragma unroll
        for (int p = 0; p < 8; p++) {
            int idx = p * 1024 + t * 4;
            float4 v = *(const float4*)(Ab + idx);
            uint4 pk;
            pk.x = packhi(v.x, v.y); pk.y = packlo(v.x, v.y);
            pk.z = packhi(v.z, v.w); pk.w = packlo(v.z, v.w);
            *(uint4*)&Aps[idx >> 7][(idx & 127) >> 1] = pk;
        }
    }

    // ---- stage FULL B tile (all 8 k-chunks), thread stages slots s0, s0+2 ----
    int scol = t & 127, s0 = t >> 7;
    const float* WpA = W + colBase + scol;
#pragma unroll
    for (int kc = 0; kc < 8; kc++) {
#pragma unroll
        for (int q = 0; q < 2; q++) {
            int s = s0 + q * 2;
            const float* p = WpA + (size_t)(kc * 16 + 2 * s) * HO;
            float w0 = p[0], w1 = p[HO], w2 = p[8 * HO], w3 = p[9 * HO];
            Bs[kc][scol][s] = make_float4(__uint_as_float(packhi(w0, w1)),
                                          __uint_as_float(packhi(w2, w3)),
                                          __uint_as_float(packlo(w0, w1)),
                                          __uint_as_float(packlo(w2, w3)));
        }
    }
    __syncthreads();                     // the ONLY barrier before the epilogue

    float acc[2][4][4];
#pragma unroll
    for (int mt = 0; mt < 2; mt++)
#pragma unroll
        for (int nt = 0; nt < 4; nt++)
#pragma unroll
            for (int j = 0; j < 4; j++) acc[mt][nt][j] = 0.f;

#pragma unroll
    for (int kc = 0; kc < 8; kc++) {
        // B fragments: loaded ONCE per kc (shared across both mt tiles)
        float4 bf[4];
#pragma unroll
        for (int nt = 0; nt < 4; nt++)
            bf[nt] = Bs[kc][wc + nt * 8 + gid][tig];

#pragma unroll
        for (int mt = 0; mt < 2; mt++) {
            int r0 = wr + mt * 16 + gid, r1 = r0 + 8;
            uint2 a0 = Aps[r0][kc * 8 + tig];         // row0, k-lo  (hi,lo)
            uint2 a1 = Aps[r1][kc * 8 + tig];         // row1, k-lo
            uint2 a2 = Aps[r0][kc * 8 + 4 + tig];     // row0, k-hi
            uint2 a3 = Aps[r1][kc * 8 + 4 + tig];     // row1, k-hi
#pragma unroll
            for (int nt = 0; nt < 4; nt++) {
                uint32_t bh0 = __float_as_uint(bf[nt].x), bh1 = __float_as_uint(bf[nt].y);
                uint32_t bl0 = __float_as_uint(bf[nt].z), bl1 = __float_as_uint(bf[nt].w);
#define MMA16(A0,A1,A2,A3,B0,B1)                                             \
                asm volatile(                                                 \
                    "mma.sync.aligned.m16n8k16.row.col.f32.bf16.bf16.f32 "    \
                    "{%0,%1,%2,%3}, {%4,%5,%6,%7}, {%8,%9}, {%0,%1,%2,%3};"   \
                    : "+f"(acc[mt][nt][0]), "+f"(acc[mt][nt][1]),             \
                      "+f"(acc[mt][nt][2]), "+f"(acc[mt][nt][3])              \
                    : "r"(A0), "r"(A1), "r"(A2), "r"(A3), "r"(B0), "r"(B1))
                MMA16(a0.x, a1.x, a2.x, a3.x, bh0, bh1);   // hi*hi
                MMA16(a0.x, a1.x, a2.x, a3.x, bl0, bl1);   // hi*lo
                MMA16(a0.y, a1.y, a2.y, a3.y, bh0, bh1);   // lo*hi
#undef MMA16
            }
        }
    }

    // ---- store h (fp16) + fused att partial dots ----
    int head_l = wc >> 6;                            // 0 or 1
    int habase = (blockIdx.y * 2 + head_l) * OO;
#pragma unroll
    for (int mt = 0; mt < 2; mt++) {
        int r0 = wr + mt * 16 + gid, r1 = r0 + 8;
        float sa0 = 0.f, da0 = 0.f, sa1 = 0.f, da1 = 0.f;
#pragma unroll
        for (int nt = 0; nt < 4; nt++) {
            int cl = wc + nt * 8 + tig * 2;          // 0..127 within block tile
            int gcol = colBase + cl;
            *(__half2*)&g_hh[(size_t)(rowBase + r0) * HO + gcol] =
                __floats2half2_rn(acc[mt][nt][0], acc[mt][nt][1]);
            *(__half2*)&g_hh[(size_t)(rowBase + r1) * HO + gcol] =
                __floats2half2_rn(acc[mt][nt][2], acc[mt][nt][3]);
            int ch = cl & 63;                        // col within head
            float as0 = att_src[habase + ch], as1 = att_src[habase + ch + 1];
            float ad0 = att_dst[habase + ch], ad1 = att_dst[habase + ch + 1];
            sa0 += acc[mt][nt][0] * as0 + acc[mt][nt][1] * as1;
            da0 += acc[mt][nt][0] * ad0 + acc[mt][nt][1] * ad1;
            sa1 += acc[mt][nt][2] * as0 + acc[mt][nt][3] * as1;
            da1 += acc[mt][nt][2] * ad0 + acc[mt][nt][3] * ad1;
        }
#pragma unroll
        for (int d = 1; d < 4; d <<= 1) {            // reduce over tig
            sa0 += __shfl_xor_sync(0xffffffffu, sa0, d);
            da0 += __shfl_xor_sync(0xffffffffu, da0, d);
            sa1 += __shfl_xor_sync(0xffffffffu, sa1, d);
            da1 += __shfl_xor_sync(0xffffffffu, da1, d);
        }
        if (tig == 0) {
            int chh = (wc >> 5) & 1;                 // which 32-col half of the head
            red[r0][head_l][chh] = make_float2(sa0, da0);
            red[r1][head_l][chh] = make_float2(sa1, da1);
        }
    }
    __syncthreads();
    if (t < 128) {
        int row = t & 63, hl = t >> 6;
        float2 a = red[row][hl][0], b = red[row][hl][1];
        int grow = rowBase + row;
        int head = blockIdx.y * 2 + hl;
        g_asrc[grow * 4 + head] = a.x + b.x;
        g_adst[grow * 4 + head] = a.y + b.y;
    }
}

// ---------------- fused segment-softmax + aggregation (no-max exp) ----------
__device__ __forceinline__ float lrelu(float a) {
    return fmaxf(a, 0.f) + 0.2f * fminf(a, 0.f);
}

__global__ __launch_bounds__(256) void agg_kernel(float* __restrict__ out,
                                                  const float* __restrict__ bias) {
    __shared__ float4 s_w[8][32];
    __shared__ int    s_idx[8][32];

    int gw = (blockIdx.x * blockDim.x + threadIdx.x) >> 5;   // 0..MM-1 exact
    int w = threadIdx.x >> 5;
    int lane = threadIdx.x & 31;
    int n = gw >> 2;
    int b = gw & 3;
    int beg = g_off[n], end = g_off[n + 1];

    float4 ad = *(const float4*)&g_adst[(b * NN + n) * 4];
    float4 ce = g_cedge;
    int myhead = lane >> 3;
    const __half* hbase = g_hh + (size_t)(b * NN) * HO + lane * 8;

    float S0 = 0.f, S1 = 0.f, S2 = 0.f, S3 = 0.f;   // per-lane partials
    float acc[8] = {0, 0, 0, 0, 0, 0, 0, 0};

    for (int c0 = beg; c0 < end; c0 += 32) {
        int i = c0 + lane;
        float p0 = 0.f, p1 = 0.f, p2 = 0.f, p3 = 0.f;
        int sidx = 0;
        if (i < end) {
            int2 e = g_cs[i];
            sidx = e.x;
            float ww = __int_as_float(e.y);
            float4 as = *(const float4*)&g_asrc[(b * NN + sidx) * 4];
            p0 = __expf(lrelu(as.x + ad.x + ww * ce.x));
            p1 = __expf(lrelu(as.y + ad.y + ww * ce.y));
            p2 = __expf(lrelu(as.z + ad.z + ww * ce.z));
            p3 = __expf(lrelu(as.w + ad.w + ww * ce.w));
            S0 += p0; S1 += p1; S2 += p2; S3 += p3;
        }
        s_idx[w][lane] = sidx;
        s_w[w][lane] = make_float4(p0, p1, p2, p3);
        __syncwarp();

        int cnt = min(32, end - c0);
#pragma unroll 8
        for (int j = 0; j < cnt; j++) {
            int sj = s_idx[w][j];
            float wj = ((const float*)&s_w[w][j])[myhead];
            int4 pk = *(const int4*)(hbase + (size_t)sj * HO);
            float2 f0 = __half22float2(*(__half2*)&pk.x);
            float2 f1 = __half22float2(*(__half2*)&pk.y);
            float2 f2 = __half22float2(*(__half2*)&pk.z);
            float2 f3 = __half22float2(*(__half2*)&pk.w);
            acc[0] = fmaf(wj, f0.x, acc[0]); acc[1] = fmaf(wj, f0.y, acc[1]);
            acc[2] = fmaf(wj, f1.x, acc[2]); acc[3] = fmaf(wj, f1.y, acc[3]);
            acc[4] = fmaf(wj, f2.x, acc[4]); acc[5] = fmaf(wj, f2.y, acc[5]);
            acc[6] = fmaf(wj, f3.x, acc[6]); acc[7] = fmaf(wj, f3.y, acc[7]);
        }
        __syncwarp();
    }

    // one warp-reduction of S per head, at the end only
#pragma unroll
    for (int d = 16; d; d >>= 1) {
        S0 += __shfl_xor_sync(0xffffffffu, S0, d);
        S1 += __shfl_xor_sync(0xffffffffu, S1, d);
        S2 += __shfl_xor_sync(0xffffffffu, S2, d);
        S3 += __shfl_xor_sync(0xffffffffu, S3, d);
    }
    float Sh = (myhead == 0) ? S0 : (myhead == 1) ? S1 : (myhead == 2) ? S2 : S3;
    float r = 1.f / fmaxf(Sh, 1e-16f);
#pragma unroll
    for (int k = 0; k < 8; k++) acc[k] *= r;

    // mean over heads: lanes l, l^8, l^16, l^24 hold same o, different h
#pragma unroll
    for (int k = 0; k < 8; k++) {
        float v = acc[k];
        v += __shfl_xor_sync(0xffffffffu, v, 8);
        v += __shfl_xor_sync(0xffffffffu, v, 16);
        acc[k] = v;
    }
    if (lane < 8) {
        float* op = out + ((size_t)b * NN + n) * OO + lane * 8;
#pragma unroll
        for (int k = 0; k < 8; k++)
            op[k] = acc[k] * 0.25f + bias[lane * 8 + k];
    }
}

// ---------------- launch ----------------------------------------------------
extern "C" void kernel_launch(void* const* d_in, const int* in_sizes, int n_in,
                              void* d_out, int out_size) {
    const float* x        = (const float*)d_in[0];
    const void*  ei       = d_in[1];
    const float* ea       = (const float*)d_in[2];
    const float* Wsrc     = (const float*)d_in[3];
    const float* att_src  = (const float*)d_in[4];
    const float* att_dst  = (const float*)d_in[5];
    const float* Wedge    = (const float*)d_in[6];
    const float* att_edge = (const float*)d_in[7];
    const float* bias     = (const float*)d_in[8];
    float* out = (float*)d_out;

    static cudaStream_t s_csr = nullptr;
    static cudaEvent_t  ev_fork = nullptr, ev_join = nullptr;
    if (s_csr == nullptr) {
        cudaStreamCreateWithFlags(&s_csr, cudaStreamNonBlocking);
        cudaEventCreateWithFlags(&ev_fork, cudaEventDisableTiming);
        cudaEventCreateWithFlags(&ev_join, cudaEventDisableTiming);
        cudaFuncSetAttribute(gemm_kernel,
                             cudaFuncAttributeMaxDynamicSharedMemorySize,
                             GEMM_SMEM);
    }

    // fork: CSR chain on side stream, GEMM on main stream, join before agg
    cudaEventRecord(ev_fork, 0);
    cudaStreamWaitEvent(s_csr, ev_fork, 0);

    hist_kernel<<<EE / 256, 256, 0, s_csr>>>((const int*)ei, Wedge, att_edge);
    scan_kernel<<<1, 1024, 0, s_csr>>>();
    scatter_kernel<<<EE / 256, 256, 0, s_csr>>>((const int*)ei, ea);
    cudaEventRecord(ev_join, s_csr);

    gemm_kernel<<<dim3(MM / 64, HO / 128), 256, GEMM_SMEM>>>(x, Wsrc, att_src, att_dst);

    cudaStreamWaitEvent(0, ev_join, 0);
    agg_kernel<<<MM / 8, 256>>>(out, bias);
}